// round 9
// baseline (speedup 1.0000x reference)
#include <cuda_runtime.h>
#include <cuda_bf16.h>
#include <math.h>

// Problem constants
#define B_  16
#define C_  4
#define J_  19
#define T_  256
#define S_  10
#define NCH (C_*J_*T_)          // 19456 BN channels
#define NPIX (B_*T_*S_)         // 40960 pixels
#define EPSV 1e-5f

#define PPB 8                   // pixels per block
#define NCOL 160                // 8 px x 20 cols
#define AST 160                 // activation row stride
#define NTH 320                 // 8 d-groups x 40 col-groups

typedef unsigned long long u64;

// ---- f32x2 packed-math helpers ------------------------------------------------
__device__ __forceinline__ u64 dup2(float a) {
    u64 r; asm("mov.b64 %0, {%1, %1};" : "=l"(r) : "f"(a)); return r;
}
__device__ __forceinline__ void upk2(u64 v, float& lo, float& hi) {
    asm("mov.b64 {%0, %1}, %2;" : "=f"(lo), "=f"(hi) : "l"(v));
}
__device__ __forceinline__ void fma2(u64& d, u64 a, u64 b) {
    asm("fma.rn.f32x2 %0, %1, %2, %0;" : "+l"(d) : "l"(a), "l"(b));
}
__device__ __forceinline__ void lds_v2u64(const float* p, u64& lo, u64& hi) {
    unsigned a = (unsigned)__cvta_generic_to_shared(p);
    asm("ld.shared.v2.u64 {%0, %1}, [%2];" : "=l"(lo), "=l"(hi) : "r"(a));
}

// ---------------- device scratch ----------------------------------------------
__device__ float g_bn_a[NCH];
__device__ float g_bn_b[NCH];
__device__ float g_w1t[C_*64];      // w1t[c][d]
__device__ float g_w2t[64*64];      // w2t[k][d]
__device__ float g_Mt[64*64];       // Mt[b][a]
__device__ float g_v[64];
__device__ float g_xn[(size_t)NPIX * 76];   // normalized input, pixel-major

// ---------------- kernel 1: BN statistics ---------------------------------------
__global__ void bn_stats_kernel(const float* __restrict__ x,
                                const float* __restrict__ gamma,
                                const float* __restrict__ beta) {
    int ch = blockIdx.x * 8 + (threadIdx.x >> 5);
    if (ch >= NCH) return;
    int lane = threadIdx.x & 31;
    float s = 0.f, ss = 0.f;
    for (int e = lane; e < B_ * S_; e += 32) {
        int b = e / S_, si = e % S_;
        float v = x[(b * NCH + ch) * S_ + si];
        s += v; ss += v * v;
    }
    #pragma unroll
    for (int off = 16; off; off >>= 1) {
        s  += __shfl_xor_sync(0xffffffffu, s,  off);
        ss += __shfl_xor_sync(0xffffffffu, ss, off);
    }
    if (lane == 0) {
        const float inv_n = 1.f / (float)(B_ * S_);
        float mean = s * inv_n;
        float var  = ss * inv_n - mean * mean;
        float a = gamma[ch] * rsqrtf(var + EPSV);
        g_bn_a[ch] = a;
        g_bn_b[ch] = beta[ch] - mean * a;
    }
}

// ---------------- kernel 2: precompute M, v, transposed weights -----------------
__global__ void setup_kernel(const float* __restrict__ w1,
                             const float* __restrict__ w2,
                             const float* __restrict__ ws1,
                             const float* __restrict__ bs1,
                             const float* __restrict__ ws2) {
    int idx = blockIdx.x * blockDim.x + threadIdx.x;
    if (idx < 4096) {
        int b = idx >> 6, a = idx & 63;
        float acc = 0.f;
        #pragma unroll 4
        for (int s = 0; s < 128; ++s)
            acc += ws1[s * 64 + a] * ws2[s * 64 + b];
        g_Mt[b * 64 + a] = acc;
        g_w2t[idx] = w2[(idx & 63) * 64 + (idx >> 6)];
    }
    if (idx < C_ * 64) g_w1t[idx] = w1[(idx & 63) * C_ + (idx >> 6)];
    if (idx < 64) {
        float acc = 0.f;
        #pragma unroll 4
        for (int s = 0; s < 128; ++s)
            acc += ws2[s * 64 + idx] * bs1[s];
        g_v[idx] = acc;
    }
}

// ---------------- kernel 3: BN-apply + transpose to pixel-major -----------------
#define XTK 8
__global__ void xn_kernel(const float* __restrict__ x) {
    __shared__ float sa[76 * XTK];
    __shared__ float sb[76 * XTK];
    __shared__ float tile[80 * 80];
    int b  = blockIdx.x >> 5;
    int t0 = (blockIdx.x & 31) * XTK;
    int tid = threadIdx.x;

    for (int u = tid; u < 76 * XTK; u += 256) {
        int ch = u / XTK, tt = u % XTK;
        sa[u] = g_bn_a[ch * 256 + t0 + tt];
        sb[u] = g_bn_b[ch * 256 + t0 + tt];
    }
    __syncthreads();

    for (int u = tid; u < 76 * 20; u += 256) {
        int ch = u / 20, i4 = (u % 20) * 4;
        float4 v = *(const float4*)&x[((size_t)(b * 76 + ch)) * 2560 + t0 * 10 + i4];
        #pragma unroll
        for (int q = 0; q < 4; ++q) {
            int i = i4 + q;
            int tt = i / 10;
            tile[i * 80 + ch] = (&v.x)[q] * sa[ch * XTK + tt] + sb[ch * XTK + tt];
        }
    }
    __syncthreads();

    for (int u = tid; u < 80 * 19; u += 256) {
        int i = u / 19, chq = u % 19;
        float4 v = *(float4*)&tile[i * 80 + chq * 4];
        *(float4*)&g_xn[((size_t)(b * 2560 + t0 * 10 + i)) * 76 + chq * 4] = v;
    }
}

// ---------------- smem layout (float offsets) ----------------------------------
#define OFF_W1T   0        // 256
#define OFF_B1    256      // 64
#define OFF_B2    320      // 64
#define OFF_V     384      // 64
#define OFF_SWB   448      // 4096 time-shared: W2T -> Mt -> W
#define OFF_LT    4544     // 8*380 = 3040, [p][j][k(20)]
#define OFF_VH    7584     // 160
#define OFF_A1    7744     // 64*160 = 10240 : h1 -> G -> AGG
#define OFF_A2    17984    // 64*160 = 10240 : H (front aliased as XN)
#define SMEM_FLOATS 28224
#define SMEM_BYTES (SMEM_FLOATS * 4)   // 112,896 B -> 2 blocks/SM
#define OFF_XN    OFF_A2   // 4*160 = 640, dead once C writes A2

__global__ __launch_bounds__(NTH, 2)
void geo_gcn_main_kernel(const float* __restrict__ b1g,
                         const float* __restrict__ b2g,
                         const float* __restrict__ Wg,
                         float* __restrict__ out) {
    extern __shared__ float sm[];
    const int tid = threadIdx.x;
    const int pix0 = blockIdx.x * PPB;

    // ---- prologue: SWB=W2T, W1T, biases, v, XN ----
    for (int q = tid; q < 1024; q += NTH)
        *(float4*)&sm[OFF_SWB + q * 4] = *(const float4*)&g_w2t[q * 4];
    if (tid < 64) {
        *(float4*)&sm[OFF_W1T + tid * 4] = *(const float4*)&g_w1t[tid * 4];
        sm[OFF_B1 + tid] = b1g[tid];
        sm[OFF_B2 + tid] = b2g[tid];
        sm[OFF_V  + tid] = g_v[tid];
    }
    if (tid < 152) {
        float4 v = *(const float4*)&g_xn[(size_t)pix0 * 76 + tid * 4];
        int g = tid * 4;
        int p = g / 76, off = g % 76;
        #pragma unroll
        for (int u = 0; u < 4; ++u) {
            int ch = off + u;
            int c = ch / 19, j = ch % 19;
            sm[OFF_XN + c * AST + p * 20 + j] = (&v.x)[u];
        }
    } else if (tid < 160) {
        int pp = tid - 152;   // zero j=19 pads
        #pragma unroll
        for (int c = 0; c < C_; ++c)
            sm[OFF_XN + c * AST + pp * 20 + 19] = 0.f;
    }
    __syncthreads();

    // ---- warp-dedup thread mapping: 4 d-groups x 8 col-groups per warp ----
    const int l = tid & 31, w = tid >> 5;
    const int dg = ((w & 1) << 2) | (l & 3);      // 0..7
    const int cg = ((w >> 1) << 3) | (l >> 2);    // 0..39
    const int d0 = dg * 8, col0 = cg * 4;

    // ================= Phase B: h1 = relu(W1 xn + b1) -> A1 =================
    {
        u64 acc[8][2];
        #pragma unroll
        for (int i = 0; i < 8; ++i) {
            u64 bv = dup2(sm[OFF_B1 + d0 + i]);
            acc[i][0] = bv; acc[i][1] = bv;
        }
        #pragma unroll
        for (int k = 0; k < C_; ++k) {
            float4 w0 = *(const float4*)&sm[OFF_W1T + k * 64 + d0];
            float4 w1 = *(const float4*)&sm[OFF_W1T + k * 64 + d0 + 4];
            u64 a01, a23;
            lds_v2u64(&sm[OFF_XN + k * AST + col0], a01, a23);
            #pragma unroll
            for (int i = 0; i < 8; ++i) {
                u64 wd = dup2(i < 4 ? (&w0.x)[i] : (&w1.x)[i - 4]);
                fma2(acc[i][0], wd, a01);
                fma2(acc[i][1], wd, a23);
            }
        }
        #pragma unroll
        for (int i = 0; i < 8; ++i) {
            float v0, v1, v2, v3;
            upk2(acc[i][0], v0, v1); upk2(acc[i][1], v2, v3);
            *(float4*)&sm[OFF_A1 + (d0 + i) * AST + col0] =
                make_float4(fmaxf(v0,0.f), fmaxf(v1,0.f), fmaxf(v2,0.f), fmaxf(v3,0.f));
        }
    }
    __syncthreads();

    // ================= Phase C: H = relu(W2 h1 + b2) -> A2 =================
    {
        u64 acc[8][2];
        #pragma unroll
        for (int i = 0; i < 8; ++i) {
            u64 bv = dup2(sm[OFF_B2 + d0 + i]);
            acc[i][0] = bv; acc[i][1] = bv;
        }
        #pragma unroll 4
        for (int k = 0; k < 64; ++k) {
            float4 w0 = *(const float4*)&sm[OFF_SWB + k * 64 + d0];
            float4 w1 = *(const float4*)&sm[OFF_SWB + k * 64 + d0 + 4];
            u64 a01, a23;
            lds_v2u64(&sm[OFF_A1 + k * AST + col0], a01, a23);
            #pragma unroll
            for (int i = 0; i < 8; ++i) {
                u64 wd = dup2(i < 4 ? (&w0.x)[i] : (&w1.x)[i - 4]);
                fma2(acc[i][0], wd, a01);
                fma2(acc[i][1], wd, a23);
            }
        }
        #pragma unroll
        for (int i = 0; i < 8; ++i) {
            float v0, v1, v2, v3;
            upk2(acc[i][0], v0, v1); upk2(acc[i][1], v2, v3);
            *(float4*)&sm[OFF_A2 + (d0 + i) * AST + col0] =
                make_float4(fmaxf(v0,0.f), fmaxf(v1,0.f), fmaxf(v2,0.f), fmaxf(v3,0.f));
        }
    }
    __syncthreads();
    // reload SWB = Mt
    for (int q = tid; q < 1024; q += NTH)
        *(float4*)&sm[OFF_SWB + q * 4] = *(const float4*)&g_Mt[q * 4];
    __syncthreads();

    // ================= Phase D: G = M H -> A1 =================
    {
        u64 acc[8][2];
        #pragma unroll
        for (int i = 0; i < 8; ++i) { acc[i][0] = 0ull; acc[i][1] = 0ull; }
        #pragma unroll 4
        for (int k = 0; k < 64; ++k) {
            float4 w0 = *(const float4*)&sm[OFF_SWB + k * 64 + d0];
            float4 w1 = *(const float4*)&sm[OFF_SWB + k * 64 + d0 + 4];
            u64 a01, a23;
            lds_v2u64(&sm[OFF_A2 + k * AST + col0], a01, a23);
            #pragma unroll
            for (int i = 0; i < 8; ++i) {
                u64 wd = dup2(i < 4 ? (&w0.x)[i] : (&w1.x)[i - 4]);
                fma2(acc[i][0], wd, a01);
                fma2(acc[i][1], wd, a23);
            }
        }
        #pragma unroll
        for (int i = 0; i < 8; ++i) {
            float v0, v1, v2, v3;
            upk2(acc[i][0], v0, v1); upk2(acc[i][1], v2, v3);
            *(float4*)&sm[OFF_A1 + (d0 + i) * AST + col0] = make_float4(v0, v1, v2, v3);
        }
    }
    __syncthreads();

    // ===== Phase F: logits LT[p][j][k] = sum_a H[a][j] G[a][k]; vh[p][k] =====
    if (tid < 200) {
        int p  = tid / 25, r = tid % 25;
        int j0 = (r % 5) * 4, k0 = (r / 5) * 4;
        u64 acc2[4][2];
        #pragma unroll
        for (int e = 0; e < 4; ++e) { acc2[e][0] = 0ull; acc2[e][1] = 0ull; }
        #pragma unroll 4
        for (int a = 0; a < 64; ++a) {
            float4 h4 = *(const float4*)&sm[OFF_A2 + a * AST + p * 20 + j0];
            u64 g01, g23;
            lds_v2u64(&sm[OFF_A1 + a * AST + p * 20 + k0], g01, g23);
            #pragma unroll
            for (int e = 0; e < 4; ++e) {
                u64 hd = dup2((&h4.x)[e]);
                fma2(acc2[e][0], hd, g01);
                fma2(acc2[e][1], hd, g23);
            }
        }
        #pragma unroll
        for (int e = 0; e < 4; ++e) {
            if (j0 + e < J_) {
                float l0, l1, l2, l3;
                upk2(acc2[e][0], l0, l1); upk2(acc2[e][1], l2, l3);
                *(float4*)&sm[OFF_LT + p * 380 + (j0 + e) * 20 + k0] =
                    make_float4(l0, l1, l2, l3);
            }
        }
    } else if (tid < 280) {
        for (int u = tid - 200; u < 160; u += 80) {
            int p = u / 20, k = u % 20;
            float a = 0.f;
            #pragma unroll 8
            for (int b = 0; b < 64; ++b)
                a += sm[OFF_V + b] * sm[OFF_A2 + b * AST + p * 20 + k];
            sm[OFF_VH + u] = a;
        }
    }
    __syncthreads();

    // ===== softmax (tid<152) ; SWB=W reload (tid>=152) =====
    if (tid < 152) {
        int p = tid / J_, j = tid % J_;
        int lb = OFF_LT + p * 380 + j * 20;
        float l[J_];
        float mx = -1e30f;
        #pragma unroll
        for (int k = 0; k < J_; ++k) {
            l[k] = sm[lb + k] + sm[OFF_VH + p * 20 + k];
            mx = fmaxf(mx, l[k]);
        }
        float sum = 0.f;
        #pragma unroll
        for (int k = 0; k < J_; ++k) { l[k] = __expf(l[k] - mx); sum += l[k]; }
        float inv = 1.f / sum;
        #pragma unroll
        for (int k = 0; k < J_; ++k) sm[lb + k] = l[k] * inv;
        sm[lb + 19] = 0.f;      // zero the k=19 pad for vectorized AGG
    } else {
        for (int q = tid - 152; q < 1024; q += 168)
            *(float4*)&sm[OFF_SWB + q * 4] = *(const float4*)&Wg[q * 4];
    }
    __syncthreads();

    // ===== AGG[c][j*8+p] = sum_k H[c][p*20+k] att[p][j][k] -> A1 (float4 k) =====
    {
        int c0 = (tid & 7) * 8;
        int rest = tid >> 3;
        int p = rest & 7;
        int j0 = (rest >> 3) * 4;
        float acc[8][4];
        #pragma unroll
        for (int i = 0; i < 8; ++i)
            #pragma unroll
            for (int r = 0; r < 4; ++r) acc[i][r] = 0.f;
        #pragma unroll
        for (int kc = 0; kc < 20; kc += 4) {
            float4 h4[8], a4[4];
            #pragma unroll
            for (int i = 0; i < 8; ++i)
                h4[i] = *(const float4*)&sm[OFF_A2 + (c0 + i) * AST + p * 20 + kc];
            #pragma unroll
            for (int r = 0; r < 4; ++r)
                a4[r] = *(const float4*)&sm[OFF_LT + p * 380 + (j0 + r) * 20 + kc];
            #pragma unroll
            for (int i = 0; i < 8; ++i)
                #pragma unroll
                for (int r = 0; r < 4; ++r) {
                    acc[i][r] += h4[i].x * a4[r].x;
                    acc[i][r] += h4[i].y * a4[r].y;
                    acc[i][r] += h4[i].z * a4[r].z;
                    acc[i][r] += h4[i].w * a4[r].w;
                }
        }
        #pragma unroll
        for (int i = 0; i < 8; ++i)
            #pragma unroll
            for (int r = 0; r < 4; ++r)
                if (j0 + r < J_)
                    sm[OFF_A1 + (c0 + i) * AST + (j0 + r) * 8 + p] = acc[i][r];
    }
    __syncthreads();

    // ===== OUT: out[o][j, px] = sum_c W[c][o] AGG[c][col] =====
    {
        u64 acc[8][2];
        #pragma unroll
        for (int i = 0; i < 8; ++i) { acc[i][0] = 0ull; acc[i][1] = 0ull; }
        #pragma unroll 4
        for (int k = 0; k < 64; ++k) {
            float4 w0 = *(const float4*)&sm[OFF_SWB + k * 64 + d0];
            float4 w1 = *(const float4*)&sm[OFF_SWB + k * 64 + d0 + 4];
            u64 a01, a23;
            lds_v2u64(&sm[OFF_A1 + k * AST + col0], a01, a23);
            #pragma unroll
            for (int i = 0; i < 8; ++i) {
                u64 wd = dup2(i < 4 ? (&w0.x)[i] : (&w1.x)[i - 4]);
                fma2(acc[i][0], wd, a01);
                fma2(acc[i][1], wd, a23);
            }
        }
        if (cg < 38) {
            int j  = cg >> 1;
            int pb = (cg & 1) * 4;
            int b    = pix0 / 2560;
            int ts0  = pix0 % 2560;
            #pragma unroll
            for (int i = 0; i < 8; ++i) {
                float v0, v1, v2, v3;
                upk2(acc[i][0], v0, v1); upk2(acc[i][1], v2, v3);
                *(float4*)&out[((size_t)((b * 64 + d0 + i) * J_ + j)) * 2560 + ts0 + pb] =
                    make_float4(v0, v1, v2, v3);
            }
        }
    }
}

// ------------------------------ launcher --------------------------------------
extern "C" void kernel_launch(void* const* d_in, const int* in_sizes, int n_in,
                              void* d_out, int out_size) {
    const float* x     = (const float*)d_in[0];
    const float* gamma = (const float*)d_in[1];
    const float* beta  = (const float*)d_in[2];
    const float* w1    = (const float*)d_in[3];
    const float* b1    = (const float*)d_in[4];
    const float* w2    = (const float*)d_in[5];
    const float* b2    = (const float*)d_in[6];
    const float* ws1   = (const float*)d_in[7];
    const float* bs1   = (const float*)d_in[8];
    const float* ws2   = (const float*)d_in[9];
    // d_in[10] = bs2 (softmax-invariant), d_in[11] = W
    const float* W     = (const float*)d_in[11];
    float* out = (float*)d_out;

    cudaFuncSetAttribute(geo_gcn_main_kernel,
                         cudaFuncAttributeMaxDynamicSharedMemorySize, SMEM_BYTES);

    bn_stats_kernel<<<NCH / 8, 256>>>(x, gamma, beta);
    setup_kernel<<<16, 256>>>(w1, w2, ws1, bs1, ws2);
    xn_kernel<<<B_ * 32, 256>>>(x);
    geo_gcn_main_kernel<<<NPIX / PPB, NTH, SMEM_BYTES>>>(b1, b2, W, out);
}

// round 10
// speedup vs baseline: 1.3730x; 1.3730x over previous
#include <cuda_runtime.h>
#include <cuda_bf16.h>
#include <math.h>

// Problem constants
#define B_  16
#define C_  4
#define J_  19
#define T_  256
#define S_  10
#define NCH (C_*J_*T_)          // 19456 BN channels
#define NPIX (B_*T_*S_)         // 40960 pixels
#define EPSV 1e-5f

#define PPB 8                   // pixels per block
#define NCOL 160
#define AST 164                 // activation stride (mma B-frag conflict relief)
#define WST 68                  // weight stride (mma A-frag conflict-free)
#define NTH 320

typedef unsigned long long u64;
typedef unsigned int u32;

// ---- f32x2 packed helpers (scalar phases) --------------------------------------
__device__ __forceinline__ u64 dup2(float a) {
    u64 r; asm("mov.b64 %0, {%1, %1};" : "=l"(r) : "f"(a)); return r;
}
__device__ __forceinline__ void upk2(u64 v, float& lo, float& hi) {
    asm("mov.b64 {%0, %1}, %2;" : "=f"(lo), "=f"(hi) : "l"(v));
}
__device__ __forceinline__ void fma2(u64& d, u64 a, u64 b) {
    asm("fma.rn.f32x2 %0, %1, %2, %0;" : "+l"(d) : "l"(a), "l"(b));
}
__device__ __forceinline__ void lds_v2u64(const float* p, u64& lo, u64& hi) {
    unsigned a = (unsigned)__cvta_generic_to_shared(p);
    asm("ld.shared.v2.u64 {%0, %1}, [%2];" : "=l"(lo), "=l"(hi) : "r"(a));
}
// ---- tf32 helpers ---------------------------------------------------------------
__device__ __forceinline__ u32 f2tf(float f) {
    u32 u; asm("cvt.rna.tf32.f32 %0, %1;" : "=r"(u) : "f"(f)); return u;
}
__device__ __forceinline__ void mma_tf32(float d[4], const u32 a[4], const u32 b[2]) {
    asm volatile(
        "mma.sync.aligned.m16n8k8.row.col.f32.tf32.tf32.f32 "
        "{%0,%1,%2,%3}, {%4,%5,%6,%7}, {%8,%9}, {%0,%1,%2,%3};\n"
        : "+f"(d[0]), "+f"(d[1]), "+f"(d[2]), "+f"(d[3])
        : "r"(a[0]), "r"(a[1]), "r"(a[2]), "r"(a[3]), "r"(b[0]), "r"(b[1]));
}

// ---------------- device scratch ----------------------------------------------
__device__ float g_bn_a[NCH];
__device__ float g_bn_b[NCH];
__device__ float g_w1t[C_*64];      // w1t[c][d]
__device__ float g_M[64*64];        // M[a][b] = sum_s ws1[s][a]*ws2[s][b]
__device__ float g_Wt[64*64];       // Wt[o][c] = W[c][o]
__device__ float g_v[64];
__device__ float g_xn[(size_t)NPIX * 76];   // normalized input, pixel-major

// ---------------- kernel 1: BN statistics ---------------------------------------
__global__ void bn_stats_kernel(const float* __restrict__ x,
                                const float* __restrict__ gamma,
                                const float* __restrict__ beta) {
    int ch = blockIdx.x * 8 + (threadIdx.x >> 5);
    if (ch >= NCH) return;
    int lane = threadIdx.x & 31;
    float s = 0.f, ss = 0.f;
    for (int e = lane; e < B_ * S_; e += 32) {
        int b = e / S_, si = e % S_;
        float v = x[(b * NCH + ch) * S_ + si];
        s += v; ss += v * v;
    }
    #pragma unroll
    for (int off = 16; off; off >>= 1) {
        s  += __shfl_xor_sync(0xffffffffu, s,  off);
        ss += __shfl_xor_sync(0xffffffffu, ss, off);
    }
    if (lane == 0) {
        const float inv_n = 1.f / (float)(B_ * S_);
        float mean = s * inv_n;
        float var  = ss * inv_n - mean * mean;
        float a = gamma[ch] * rsqrtf(var + EPSV);
        g_bn_a[ch] = a;
        g_bn_b[ch] = beta[ch] - mean * a;
    }
}

// ---------------- kernel 2: precompute M, Wt, v, w1t -----------------------------
__global__ void setup_kernel(const float* __restrict__ w1,
                             const float* __restrict__ ws1,
                             const float* __restrict__ bs1,
                             const float* __restrict__ ws2,
                             const float* __restrict__ W) {
    int idx = blockIdx.x * blockDim.x + threadIdx.x;
    if (idx < 4096) {
        int a = idx >> 6, b = idx & 63;
        float acc = 0.f;
        #pragma unroll 4
        for (int s = 0; s < 128; ++s)
            acc += ws1[s * 64 + a] * ws2[s * 64 + b];
        g_M[a * 64 + b] = acc;
        g_Wt[idx] = W[(idx & 63) * 64 + (idx >> 6)];   // Wt[o][c] = W[c][o]
    }
    if (idx < C_ * 64) g_w1t[idx] = w1[(idx & 63) * C_ + (idx >> 6)];
    if (idx < 64) {
        float acc = 0.f;
        #pragma unroll 4
        for (int s = 0; s < 128; ++s)
            acc += ws2[s * 64 + idx] * bs1[s];
        g_v[idx] = acc;
    }
}

// ---------------- kernel 3: BN-apply + transpose to pixel-major -----------------
#define XTK 8
__global__ void xn_kernel(const float* __restrict__ x) {
    __shared__ float sa[76 * XTK];
    __shared__ float sb[76 * XTK];
    __shared__ float tile[80 * 80];
    int b  = blockIdx.x >> 5;
    int t0 = (blockIdx.x & 31) * XTK;
    int tid = threadIdx.x;

    for (int u = tid; u < 76 * XTK; u += 256) {
        int ch = u / XTK, tt = u % XTK;
        sa[u] = g_bn_a[ch * 256 + t0 + tt];
        sb[u] = g_bn_b[ch * 256 + t0 + tt];
    }
    __syncthreads();

    for (int u = tid; u < 76 * 20; u += 256) {
        int ch = u / 20, i4 = (u % 20) * 4;
        float4 v = *(const float4*)&x[((size_t)(b * 76 + ch)) * 2560 + t0 * 10 + i4];
        #pragma unroll
        for (int q = 0; q < 4; ++q) {
            int i = i4 + q;
            int tt = i / 10;
            tile[i * 80 + ch] = (&v.x)[q] * sa[ch * XTK + tt] + sb[ch * XTK + tt];
        }
    }
    __syncthreads();

    for (int u = tid; u < 80 * 19; u += 256) {
        int i = u / 19, chq = u % 19;
        float4 v = *(float4*)&tile[i * 80 + chq * 4];
        *(float4*)&g_xn[((size_t)(b * 2560 + t0 * 10 + i)) * 76 + chq * 4] = v;
    }
}

// ---------------- smem layout (float offsets) ----------------------------------
#define OFF_W1T   0        // 256
#define OFF_B1    256      // 64
#define OFF_B2    320      // 64
#define OFF_V     384      // 64
#define OFF_SWB   448      // 64*68 = 4352, time-shared: w2 -> M -> (LT/VH) -> Wt
#define OFF_A1    4800     // 64*164 = 10496 : h1 -> G -> AGG
#define OFF_A2    15296    // 64*164 = 10496 : XN -> H -> OUT-stage
#define SMEM_FLOATS 25792
#define SMEM_BYTES (SMEM_FLOATS * 4)   // 103,168 B -> 2 blocks/SM
#define OFF_XN    OFF_A2
#define OFF_LT    OFF_SWB               // 8*380 = 3040 (weights dead during F..AGG)
#define OFF_VH    (OFF_SWB + 3040)      // 160

// ---- generic tf32 mma GEMM phase: D[64 x nCols] = A(SWB,64x64) * B(offB) --------
template<int BIAS, int RELU, int CVT>
__device__ __forceinline__ void mma_phase(float* sm, int offB, int offD,
                                          int nLimit, int w, int lane) {
    u32* smu = (u32*)sm;
    const int r4 = lane >> 2, l4 = lane & 3;
    const int n0 = w * 16;
    float d[2][4][4];
    #pragma unroll
    for (int nt = 0; nt < 2; ++nt)
        #pragma unroll
        for (int mt = 0; mt < 4; ++mt) {
            float bz0 = 0.f, bz1 = 0.f;
            if (BIAS) {
                bz0 = sm[OFF_B2 + mt * 16 + r4];
                bz1 = sm[OFF_B2 + mt * 16 + 8 + r4];
            }
            d[nt][mt][0] = bz0; d[nt][mt][1] = bz0;
            d[nt][mt][2] = bz1; d[nt][mt][3] = bz1;
        }
    #pragma unroll
    for (int k0 = 0; k0 < 64; k0 += 8) {
        u32 a[4][4];
        #pragma unroll
        for (int mt = 0; mt < 4; ++mt) {
            int base = OFF_SWB + (mt * 16 + r4) * WST + k0 + l4;
            a[mt][0] = smu[base];
            a[mt][1] = smu[base + 8 * WST];
            a[mt][2] = smu[base + 4];
            a[mt][3] = smu[base + 8 * WST + 4];
        }
        u32 b[2][2];
        #pragma unroll
        for (int nt = 0; nt < 2; ++nt) {
            int n = n0 + nt * 8;
            if (n < nLimit) {
                int base = offB + (k0 + l4) * AST + n + r4;
                b[nt][0] = smu[base];
                b[nt][1] = smu[base + 4 * AST];
            }
        }
        #pragma unroll
        for (int nt = 0; nt < 2; ++nt) {
            if (n0 + nt * 8 < nLimit) {
                #pragma unroll
                for (int mt = 0; mt < 4; ++mt)
                    mma_tf32(d[nt][mt], a[mt], b[nt]);
            }
        }
    }
    // store to smem [row][col] stride AST
    #pragma unroll
    for (int nt = 0; nt < 2; ++nt) {
        int n = n0 + nt * 8;
        if (n < nLimit) {
            int col = n + l4 * 2;
            #pragma unroll
            for (int mt = 0; mt < 4; ++mt) {
                float v0 = d[nt][mt][0], v1 = d[nt][mt][1];
                float v2 = d[nt][mt][2], v3 = d[nt][mt][3];
                if (RELU) {
                    v0 = fmaxf(v0, 0.f); v1 = fmaxf(v1, 0.f);
                    v2 = fmaxf(v2, 0.f); v3 = fmaxf(v3, 0.f);
                }
                int row0 = mt * 16 + r4;
                if (CVT) {
                    *(uint2*)&smu[offD + row0 * AST + col] =
                        make_uint2(f2tf(v0), f2tf(v1));
                    *(uint2*)&smu[offD + (row0 + 8) * AST + col] =
                        make_uint2(f2tf(v2), f2tf(v3));
                } else {
                    *(float2*)&sm[offD + row0 * AST + col] = make_float2(v0, v1);
                    *(float2*)&sm[offD + (row0 + 8) * AST + col] = make_float2(v2, v3);
                }
            }
        }
    }
}

__global__ __launch_bounds__(NTH, 2)
void geo_gcn_main_kernel(const float* __restrict__ b1g,
                         const float* __restrict__ b2g,
                         const float* __restrict__ w2g,
                         float* __restrict__ out) {
    extern __shared__ float sm[];
    u32* smu = (u32*)sm;
    const int tid = threadIdx.x;
    const int pix0 = blockIdx.x * PPB;
    const int w = tid >> 5, lane = tid & 31;

    // ---- prologue: SWB = tf32(w2[d][k]) @ stride 68; W1T; biases; v; XN ----
    for (int q = tid; q < 1024; q += NTH) {
        float4 v = *(const float4*)&w2g[q * 4];
        int d = q >> 4, k4 = (q & 15) * 4;
        int base = OFF_SWB + d * WST + k4;
        smu[base]     = f2tf(v.x); smu[base + 1] = f2tf(v.y);
        smu[base + 2] = f2tf(v.z); smu[base + 3] = f2tf(v.w);
    }
    if (tid < 64) {
        *(float4*)&sm[OFF_W1T + tid * 4] = *(const float4*)&g_w1t[tid * 4];
        sm[OFF_B1 + tid] = b1g[tid];
        sm[OFF_B2 + tid] = b2g[tid];
        sm[OFF_V  + tid] = g_v[tid];
    }
    if (tid < 152) {
        float4 v = *(const float4*)&g_xn[(size_t)pix0 * 76 + tid * 4];
        int g = tid * 4;
        int p = g / 76, off = g % 76;
        #pragma unroll
        for (int u = 0; u < 4; ++u) {
            int ch = off + u;
            int c = ch / 19, j = ch % 19;
            sm[OFF_XN + c * AST + p * 20 + j] = (&v.x)[u];
        }
    } else if (tid < 160) {
        int pp = tid - 152;
        #pragma unroll
        for (int c = 0; c < C_; ++c)
            sm[OFF_XN + c * AST + pp * 20 + 19] = 0.f;
    }
    __syncthreads();

    // ================= Phase B: h1 = relu(W1 xn + b1) -> A1 (tf32) ==========
    {
        const int dg = tid / 40, cg = tid % 40;
        const int d0 = dg * 8, col0 = cg * 4;
        u64 acc[8][2];
        #pragma unroll
        for (int i = 0; i < 8; ++i) {
            u64 bv = dup2(sm[OFF_B1 + d0 + i]);
            acc[i][0] = bv; acc[i][1] = bv;
        }
        #pragma unroll
        for (int k = 0; k < C_; ++k) {
            float4 w0 = *(const float4*)&sm[OFF_W1T + k * 64 + d0];
            float4 w1 = *(const float4*)&sm[OFF_W1T + k * 64 + d0 + 4];
            u64 a01, a23;
            lds_v2u64(&sm[OFF_XN + k * AST + col0], a01, a23);
            #pragma unroll
            for (int i = 0; i < 8; ++i) {
                u64 wd = dup2(i < 4 ? (&w0.x)[i] : (&w1.x)[i - 4]);
                fma2(acc[i][0], wd, a01);
                fma2(acc[i][1], wd, a23);
            }
        }
        #pragma unroll
        for (int i = 0; i < 8; ++i) {
            float v0, v1, v2, v3;
            upk2(acc[i][0], v0, v1); upk2(acc[i][1], v2, v3);
            *(uint4*)&smu[OFF_A1 + (d0 + i) * AST + col0] =
                make_uint4(f2tf(fmaxf(v0, 0.f)), f2tf(fmaxf(v1, 0.f)),
                           f2tf(fmaxf(v2, 0.f)), f2tf(fmaxf(v3, 0.f)));
        }
    }
    __syncthreads();

    // ================= Phase C: H = relu(w2 h1 + b2) -> A2 (tf32) ===========
    mma_phase<1, 1, 1>(sm, OFF_A1, OFF_A2, 160, w, lane);
    __syncthreads();
    // reload SWB = tf32(M)
    for (int q = tid; q < 1024; q += NTH) {
        float4 v = *(const float4*)&g_M[q * 4];
        int d = q >> 4, k4 = (q & 15) * 4;
        int base = OFF_SWB + d * WST + k4;
        smu[base]     = f2tf(v.x); smu[base + 1] = f2tf(v.y);
        smu[base + 2] = f2tf(v.z); smu[base + 3] = f2tf(v.w);
    }
    __syncthreads();

    // ================= Phase D: G = M H -> A1 (f32) ==========================
    mma_phase<0, 0, 0>(sm, OFF_A2, OFF_A1, 160, w, lane);
    __syncthreads();

    // ===== Phase F: logits LT[p][j][k] = sum_a H[a][j] G[a][k]; vh[p][k] =====
    if (tid < 200) {
        int p  = tid / 25, r = tid % 25;
        int j0 = (r % 5) * 4, k0 = (r / 5) * 4;
        u64 acc2[4][2];
        #pragma unroll
        for (int e = 0; e < 4; ++e) { acc2[e][0] = 0ull; acc2[e][1] = 0ull; }
        #pragma unroll 4
        for (int a = 0; a < 64; ++a) {
            float4 h4 = *(const float4*)&sm[OFF_A2 + a * AST + p * 20 + j0];
            u64 g01, g23;
            lds_v2u64(&sm[OFF_A1 + a * AST + p * 20 + k0], g01, g23);
            #pragma unroll
            for (int e = 0; e < 4; ++e) {
                u64 hd = dup2((&h4.x)[e]);
                fma2(acc2[e][0], hd, g01);
                fma2(acc2[e][1], hd, g23);
            }
        }
        #pragma unroll
        for (int e = 0; e < 4; ++e) {
            if (j0 + e < J_) {
                float l0, l1, l2, l3;
                upk2(acc2[e][0], l0, l1); upk2(acc2[e][1], l2, l3);
                *(float4*)&sm[OFF_LT + p * 380 + (j0 + e) * 20 + k0] =
                    make_float4(l0, l1, l2, l3);
            }
        }
    } else if (tid < 280) {
        for (int u = tid - 200; u < 160; u += 80) {
            int p = u / 20, k = u % 20;
            float a = 0.f;
            #pragma unroll 8
            for (int b = 0; b < 64; ++b)
                a += sm[OFF_V + b] * sm[OFF_A2 + b * AST + p * 20 + k];
            sm[OFF_VH + u] = a;
        }
    }
    __syncthreads();

    // ===== softmax over k per (pixel, j) =====
    if (tid < 152) {
        int p = tid / J_, j = tid % J_;
        int lb = OFF_LT + p * 380 + j * 20;
        float l[J_];
        float mx = -1e30f;
        #pragma unroll
        for (int k = 0; k < J_; ++k) {
            l[k] = sm[lb + k] + sm[OFF_VH + p * 20 + k];
            mx = fmaxf(mx, l[k]);
        }
        float sum = 0.f;
        #pragma unroll
        for (int k = 0; k < J_; ++k) { l[k] = __expf(l[k] - mx); sum += l[k]; }
        float inv = 1.f / sum;
        #pragma unroll
        for (int k = 0; k < J_; ++k) sm[lb + k] = l[k] * inv;
        sm[lb + 19] = 0.f;      // zero pad for float4 AGG
    }
    __syncthreads();

    // ===== AGG[c][j*8+p] = sum_k H[c][p*20+k] att[p][j][k] -> A1 (tf32) =====
    {
        int c0 = (tid & 7) * 8;
        int rest = tid >> 3;
        int p = rest & 7;
        int j0 = (rest >> 3) * 4;
        float acc[8][4];
        #pragma unroll
        for (int i = 0; i < 8; ++i)
            #pragma unroll
            for (int r = 0; r < 4; ++r) acc[i][r] = 0.f;
        #pragma unroll
        for (int kc = 0; kc < 20; kc += 4) {
            float4 h4[8], a4[4];
            #pragma unroll
            for (int i = 0; i < 8; ++i)
                h4[i] = *(const float4*)&sm[OFF_A2 + (c0 + i) * AST + p * 20 + kc];
            #pragma unroll
            for (int r = 0; r < 4; ++r)
                a4[r] = *(const float4*)&sm[OFF_LT + p * 380 + (j0 + r) * 20 + kc];
            #pragma unroll
            for (int i = 0; i < 8; ++i)
                #pragma unroll
                for (int r = 0; r < 4; ++r) {
                    acc[i][r] += h4[i].x * a4[r].x;
                    acc[i][r] += h4[i].y * a4[r].y;
                    acc[i][r] += h4[i].z * a4[r].z;
                    acc[i][r] += h4[i].w * a4[r].w;
                }
        }
        #pragma unroll
        for (int i = 0; i < 8; ++i)
            #pragma unroll
            for (int r = 0; r < 4; ++r)
                if (j0 + r < J_)
                    smu[OFF_A1 + (c0 + i) * AST + (j0 + r) * 8 + p] = f2tf(acc[i][r]);
    }
    __syncthreads();

    // reload SWB = tf32(Wt)   (LT/VH dead now)
    for (int q = tid; q < 1024; q += NTH) {
        float4 v = *(const float4*)&g_Wt[q * 4];
        int d = q >> 4, k4 = (q & 15) * 4;
        int base = OFF_SWB + d * WST + k4;
        smu[base]     = f2tf(v.x); smu[base + 1] = f2tf(v.y);
        smu[base + 2] = f2tf(v.z); smu[base + 3] = f2tf(v.w);
    }
    __syncthreads();

    // ================= OUT: Wt * AGG -> stage into A2 (f32) ==================
    mma_phase<0, 0, 0>(sm, OFF_A1, OFF_A2, 152, w, lane);
    __syncthreads();

    // ===== coalesced global store from A2[o][j*8+p] =====
    {
        int b   = pix0 / 2560;
        int ts0 = pix0 % 2560;
        for (int v = tid; v < 64 * 38; v += NTH) {
            int o = v / 38, rr = v % 38;
            int j = rr >> 1, pb = (rr & 1) * 4;
            float4 t = *(const float4*)&sm[OFF_A2 + o * AST + j * 8 + pb];
            *(float4*)&out[((size_t)((b * 64 + o) * J_ + j)) * 2560 + ts0 + pb] = t;
        }
    }
}

// ------------------------------ launcher --------------------------------------
extern "C" void kernel_launch(void* const* d_in, const int* in_sizes, int n_in,
                              void* d_out, int out_size) {
    const float* x     = (const float*)d_in[0];
    const float* gamma = (const float*)d_in[1];
    const float* beta  = (const float*)d_in[2];
    const float* w1    = (const float*)d_in[3];
    const float* b1    = (const float*)d_in[4];
    const float* w2    = (const float*)d_in[5];
    const float* b2    = (const float*)d_in[6];
    const float* ws1   = (const float*)d_in[7];
    const float* bs1   = (const float*)d_in[8];
    const float* ws2   = (const float*)d_in[9];
    // d_in[10] = bs2 (softmax-invariant), d_in[11] = W
    const float* W     = (const float*)d_in[11];
    float* out = (float*)d_out;

    cudaFuncSetAttribute(geo_gcn_main_kernel,
                         cudaFuncAttributeMaxDynamicSharedMemorySize, SMEM_BYTES);

    bn_stats_kernel<<<NCH / 8, 256>>>(x, gamma, beta);
    setup_kernel<<<16, 256>>>(w1, ws1, bs1, ws2, W);
    xn_kernel<<<B_ * 32, 256>>>(x);
    geo_gcn_main_kernel<<<NPIX / PPB, NTH, SMEM_BYTES>>>(b1, b2, w2, out);
}

// round 11
// speedup vs baseline: 2.4942x; 1.8167x over previous
#include <cuda_runtime.h>
#include <cuda_bf16.h>
#include <math.h>

// Problem constants
#define B_  16
#define C_  4
#define J_  19
#define T_  256
#define S_  10
#define NCH (C_*J_*T_)          // 19456 BN channels
#define NPIX (B_*T_*S_)         // 40960 pixels
#define EPSV 1e-5f

#define PPB 8                   // pixels per block
#define AST 168                 // activation stride (8*l4+r4 conflict-free)
#define WST 68                  // weight stride (4*r4+l4 conflict-free)
#define NTH 320
#define LTS 28                  // LT row stride (28*r4+l4 conflict-free)
#define LTP (J_*LTS)            // 532 per-pixel LT stride

typedef unsigned long long u64;
typedef unsigned int u32;

// ---- f32x2 packed helpers (scalar phases) --------------------------------------
__device__ __forceinline__ u64 dup2(float a) {
    u64 r; asm("mov.b64 %0, {%1, %1};" : "=l"(r) : "f"(a)); return r;
}
__device__ __forceinline__ void upk2(u64 v, float& lo, float& hi) {
    asm("mov.b64 {%0, %1}, %2;" : "=f"(lo), "=f"(hi) : "l"(v));
}
__device__ __forceinline__ void fma2(u64& d, u64 a, u64 b) {
    asm("fma.rn.f32x2 %0, %1, %2, %0;" : "+l"(d) : "l"(a), "l"(b));
}
__device__ __forceinline__ void lds_v2u64(const float* p, u64& lo, u64& hi) {
    unsigned a = (unsigned)__cvta_generic_to_shared(p);
    asm("ld.shared.v2.u64 {%0, %1}, [%2];" : "=l"(lo), "=l"(hi) : "r"(a));
}
// ---- tf32 helpers ---------------------------------------------------------------
__device__ __forceinline__ u32 f2tf(float f) {
    u32 u; asm("cvt.rna.tf32.f32 %0, %1;" : "=r"(u) : "f"(f)); return u;
}
__device__ __forceinline__ void mma_tf32(float d[4], const u32 a[4], const u32 b[2]) {
    asm volatile(
        "mma.sync.aligned.m16n8k8.row.col.f32.tf32.tf32.f32 "
        "{%0,%1,%2,%3}, {%4,%5,%6,%7}, {%8,%9}, {%0,%1,%2,%3};\n"
        : "+f"(d[0]), "+f"(d[1]), "+f"(d[2]), "+f"(d[3])
        : "r"(a[0]), "r"(a[1]), "r"(a[2]), "r"(a[3]), "r"(b[0]), "r"(b[1]));
}

// ---------------- device scratch ----------------------------------------------
__device__ float g_bn_a[NCH];
__device__ float g_bn_b[NCH];
__device__ float g_w1t[C_*64];      // w1t[c][d]
__device__ float g_M[64*64];        // M[a][b]
__device__ float g_Wt[64*64];       // Wt[o][c] = W[c][o]
__device__ float g_v[64];
__device__ float g_xn[(size_t)NPIX * 76];

// ---------------- kernel 1: BN statistics ---------------------------------------
__global__ void bn_stats_kernel(const float* __restrict__ x,
                                const float* __restrict__ gamma,
                                const float* __restrict__ beta) {
    int ch = blockIdx.x * 8 + (threadIdx.x >> 5);
    if (ch >= NCH) return;
    int lane = threadIdx.x & 31;
    float s = 0.f, ss = 0.f;
    for (int e = lane; e < B_ * S_; e += 32) {
        int b = e / S_, si = e % S_;
        float v = x[(b * NCH + ch) * S_ + si];
        s += v; ss += v * v;
    }
    #pragma unroll
    for (int off = 16; off; off >>= 1) {
        s  += __shfl_xor_sync(0xffffffffu, s,  off);
        ss += __shfl_xor_sync(0xffffffffu, ss, off);
    }
    if (lane == 0) {
        const float inv_n = 1.f / (float)(B_ * S_);
        float mean = s * inv_n;
        float var  = ss * inv_n - mean * mean;
        float a = gamma[ch] * rsqrtf(var + EPSV);
        g_bn_a[ch] = a;
        g_bn_b[ch] = beta[ch] - mean * a;
    }
}

// ---------------- kernel 2: precompute M, Wt, v, w1t -----------------------------
__global__ void setup_kernel(const float* __restrict__ w1,
                             const float* __restrict__ ws1,
                             const float* __restrict__ bs1,
                             const float* __restrict__ ws2,
                             const float* __restrict__ W) {
    int idx = blockIdx.x * blockDim.x + threadIdx.x;
    if (idx < 4096) {
        int a = idx >> 6, b = idx & 63;
        float acc = 0.f;
        #pragma unroll 4
        for (int s = 0; s < 128; ++s)
            acc += ws1[s * 64 + a] * ws2[s * 64 + b];
        g_M[a * 64 + b] = acc;
        g_Wt[idx] = W[(idx & 63) * 64 + (idx >> 6)];
    }
    if (idx < C_ * 64) g_w1t[idx] = w1[(idx & 63) * C_ + (idx >> 6)];
    if (idx < 64) {
        float acc = 0.f;
        #pragma unroll 4
        for (int s = 0; s < 128; ++s)
            acc += ws2[s * 64 + idx] * bs1[s];
        g_v[idx] = acc;
    }
}

// ---------------- kernel 3: BN-apply + transpose to pixel-major -----------------
#define XTK 8
__global__ void xn_kernel(const float* __restrict__ x) {
    __shared__ float sa[76 * XTK];
    __shared__ float sb[76 * XTK];
    __shared__ float tile[80 * 80];
    int b  = blockIdx.x >> 5;
    int t0 = (blockIdx.x & 31) * XTK;
    int tid = threadIdx.x;

    for (int u = tid; u < 76 * XTK; u += 256) {
        int ch = u / XTK, tt = u % XTK;
        sa[u] = g_bn_a[ch * 256 + t0 + tt];
        sb[u] = g_bn_b[ch * 256 + t0 + tt];
    }
    __syncthreads();

    for (int u = tid; u < 76 * 20; u += 256) {
        int ch = u / 20, i4 = (u % 20) * 4;
        float4 v = *(const float4*)&x[((size_t)(b * 76 + ch)) * 2560 + t0 * 10 + i4];
        #pragma unroll
        for (int q = 0; q < 4; ++q) {
            int i = i4 + q;
            int tt = i / 10;
            tile[i * 80 + ch] = (&v.x)[q] * sa[ch * XTK + tt] + sb[ch * XTK + tt];
        }
    }
    __syncthreads();

    for (int u = tid; u < 80 * 19; u += 256) {
        int i = u / 19, chq = u % 19;
        float4 v = *(float4*)&tile[i * 80 + chq * 4];
        *(float4*)&g_xn[((size_t)(b * 2560 + t0 * 10 + i)) * 76 + chq * 4] = v;
    }
}

// ---------------- smem layout (float offsets) ----------------------------------
#define OFF_W1T   0        // 256 (VH aliases after phase B)
#define OFF_B1    256
#define OFF_B2    320
#define OFF_V     384
#define OFF_SWB   448      // 64*68 = 4352, time-shared: w2 -> M -> LT -> Wt
#define OFF_A1    4800     // 64*168 = 10752 : h1 -> G -> AGG
#define OFF_A2    15552    // 64*168 = 10752 : XN -> H
#define SMEM_FLOATS 26304
#define SMEM_BYTES (SMEM_FLOATS * 4)   // 105,216 B -> 2 blocks/SM
#define OFF_XN    OFF_A2
#define OFF_LT    OFF_SWB               // 8*532 = 4256
#define OFF_VH    OFF_W1T               // 160 (W1T dead after phase B)

// ---- tf32 mma GEMM: D[64 x nCols] = A(SWB) * B(offB); warp = 2m x 4n tiles ------
template<int BIAS, int RELU, int CVT>
__device__ __forceinline__ void mma_phase(float* sm, int offB, int offD,
                                          int nLimit, int w, int lane) {
    u32* smu = (u32*)sm;
    const int r4 = lane >> 2, l4 = lane & 3;
    const int wm = (w >= 5) ? 1 : 0;
    const int wn = w - wm * 5;
    const int m0 = wm * 32;
    const int n0 = wn * 32;
    float d[2][4][4];
    #pragma unroll
    for (int mt = 0; mt < 2; ++mt) {
        float bz0 = 0.f, bz1 = 0.f;
        if (BIAS) {
            bz0 = sm[OFF_B2 + m0 + mt * 16 + r4];
            bz1 = sm[OFF_B2 + m0 + mt * 16 + 8 + r4];
        }
        #pragma unroll
        for (int nt = 0; nt < 4; ++nt) {
            d[mt][nt][0] = bz0; d[mt][nt][1] = bz0;
            d[mt][nt][2] = bz1; d[mt][nt][3] = bz1;
        }
    }
    #pragma unroll
    for (int k0 = 0; k0 < 64; k0 += 8) {
        u32 a[2][4];
        #pragma unroll
        for (int mt = 0; mt < 2; ++mt) {
            int base = OFF_SWB + (m0 + mt * 16 + r4) * WST + k0 + l4;
            a[mt][0] = smu[base];
            a[mt][1] = smu[base + 8 * WST];
            a[mt][2] = smu[base + 4];
            a[mt][3] = smu[base + 8 * WST + 4];
        }
        u32 b[4][2];
        #pragma unroll
        for (int nt = 0; nt < 4; ++nt) {
            int n = n0 + nt * 8;
            if (n < nLimit) {
                int base = offB + (k0 + l4) * AST + n + r4;
                b[nt][0] = smu[base];
                b[nt][1] = smu[base + 4 * AST];
            }
        }
        #pragma unroll
        for (int nt = 0; nt < 4; ++nt)
            if (n0 + nt * 8 < nLimit)
                #pragma unroll
                for (int mt = 0; mt < 2; ++mt)
                    mma_tf32(d[mt][nt], a[mt], b[nt]);
    }
    #pragma unroll
    for (int mt = 0; mt < 2; ++mt)
        #pragma unroll
        for (int nt = 0; nt < 4; ++nt) {
            int n = n0 + nt * 8;
            if (n < nLimit) {
                int col = n + l4 * 2;
                int row0 = m0 + mt * 16 + r4;
                float v0 = d[mt][nt][0], v1 = d[mt][nt][1];
                float v2 = d[mt][nt][2], v3 = d[mt][nt][3];
                if (RELU) {
                    v0 = fmaxf(v0, 0.f); v1 = fmaxf(v1, 0.f);
                    v2 = fmaxf(v2, 0.f); v3 = fmaxf(v3, 0.f);
                }
                if (CVT) {
                    *(uint2*)&smu[offD + row0 * AST + col] =
                        make_uint2(f2tf(v0), f2tf(v1));
                    *(uint2*)&smu[offD + (row0 + 8) * AST + col] =
                        make_uint2(f2tf(v2), f2tf(v3));
                } else {
                    *(float2*)&sm[offD + row0 * AST + col] = make_float2(v0, v1);
                    *(float2*)&sm[offD + (row0 + 8) * AST + col] = make_float2(v2, v3);
                }
            }
        }
}

__global__ __launch_bounds__(NTH, 2)
void geo_gcn_main_kernel(const float* __restrict__ b1g,
                         const float* __restrict__ b2g,
                         const float* __restrict__ w2g,
                         float* __restrict__ out) {
    extern __shared__ float sm[];
    u32* smu = (u32*)sm;
    const int tid = threadIdx.x;
    const int pix0 = blockIdx.x * PPB;
    const int w = tid >> 5, lane = tid & 31;
    const int r4 = lane >> 2, l4 = lane & 3;

    // ---- prologue ----
    for (int q = tid; q < 1024; q += NTH) {
        float4 v = *(const float4*)&w2g[q * 4];
        int d = q >> 4, k4 = (q & 15) * 4;
        int base = OFF_SWB + d * WST + k4;
        smu[base]     = f2tf(v.x); smu[base + 1] = f2tf(v.y);
        smu[base + 2] = f2tf(v.z); smu[base + 3] = f2tf(v.w);
    }
    if (tid < 64) {
        *(float4*)&sm[OFF_W1T + tid * 4] = *(const float4*)&g_w1t[tid * 4];
        sm[OFF_B1 + tid] = b1g[tid];
        sm[OFF_B2 + tid] = b2g[tid];
        sm[OFF_V  + tid] = g_v[tid];
    }
    if (tid < 152) {
        float4 v = *(const float4*)&g_xn[(size_t)pix0 * 76 + tid * 4];
        int g = tid * 4;
        int p = g / 76, off = g % 76;
        #pragma unroll
        for (int u = 0; u < 4; ++u) {
            int ch = off + u;
            int c = ch / 19, j = ch % 19;
            sm[OFF_XN + c * AST + p * 20 + j] = (&v.x)[u];
        }
    } else if (tid < 160) {
        int pp = tid - 152;
        #pragma unroll
        for (int c = 0; c < C_; ++c)
            sm[OFF_XN + c * AST + pp * 20 + 19] = 0.f;
    } else if (tid < 288) {
        // zero A2 pad cols 160..167 (NaN safety for mma k-overreach)
        int u = tid - 160;             // 0..127
        int row = u >> 1, colb = 160 + (u & 1) * 4;
        *(float4*)&sm[OFF_A2 + row * AST + colb] = make_float4(0.f, 0.f, 0.f, 0.f);
    }
    __syncthreads();

    // ================= Phase B: h1 = relu(W1 xn + b1) -> A1 (tf32) ==========
    {
        const int dg = tid / 40, cg = tid % 40;
        const int d0 = dg * 8, col0 = cg * 4;
        u64 acc[8][2];
        #pragma unroll
        for (int i = 0; i < 8; ++i) {
            u64 bv = dup2(sm[OFF_B1 + d0 + i]);
            acc[i][0] = bv; acc[i][1] = bv;
        }
        #pragma unroll
        for (int k = 0; k < C_; ++k) {
            float4 w0 = *(const float4*)&sm[OFF_W1T + k * 64 + d0];
            float4 w1 = *(const float4*)&sm[OFF_W1T + k * 64 + d0 + 4];
            u64 a01, a23;
            lds_v2u64(&sm[OFF_XN + k * AST + col0], a01, a23);
            #pragma unroll
            for (int i = 0; i < 8; ++i) {
                u64 wd = dup2(i < 4 ? (&w0.x)[i] : (&w1.x)[i - 4]);
                fma2(acc[i][0], wd, a01);
                fma2(acc[i][1], wd, a23);
            }
        }
        #pragma unroll
        for (int i = 0; i < 8; ++i) {
            float v0, v1, v2, v3;
            upk2(acc[i][0], v0, v1); upk2(acc[i][1], v2, v3);
            *(uint4*)&smu[OFF_A1 + (d0 + i) * AST + col0] =
                make_uint4(f2tf(fmaxf(v0, 0.f)), f2tf(fmaxf(v1, 0.f)),
                           f2tf(fmaxf(v2, 0.f)), f2tf(fmaxf(v3, 0.f)));
        }
    }
    __syncthreads();

    // ================= Phase C: H = relu(w2 h1 + b2) -> A2 (tf32) ===========
    mma_phase<1, 1, 1>(sm, OFF_A1, OFF_A2, 160, w, lane);
    __syncthreads();
    // reload SWB = tf32(M)
    for (int q = tid; q < 1024; q += NTH) {
        float4 v = *(const float4*)&g_M[q * 4];
        int d = q >> 4, k4 = (q & 15) * 4;
        int base = OFF_SWB + d * WST + k4;
        smu[base]     = f2tf(v.x); smu[base + 1] = f2tf(v.y);
        smu[base + 2] = f2tf(v.z); smu[base + 3] = f2tf(v.w);
    }
    __syncthreads();

    // ================= Phase D: G = M H -> A1 (tf32) =========================
    mma_phase<0, 0, 1>(sm, OFF_A2, OFF_A1, 160, w, lane);
    __syncthreads();

    // ===== Phase F (mma): logits L[p][j][k] = sum_a H[a][j] G[a][k] -> LT =====
    // warps 0..7: pixel p = w;  warps 8,9: vh[p*20+k] = sum_b v[b] H[b][col]
    if (w < 8) {
        const int p20 = w * 20;
        float d[2][3][4];
        #pragma unroll
        for (int mt = 0; mt < 2; ++mt)
            #pragma unroll
            for (int nt = 0; nt < 3; ++nt)
                #pragma unroll
                for (int e = 0; e < 4; ++e) d[mt][nt][e] = 0.f;
        #pragma unroll
        for (int ks = 0; ks < 8; ++ks) {
            int kb = ks * 8 + l4;
            u32 a[2][4];
            // mt0: j rows r4, r4+8
            a[0][0] = smu[OFF_A2 + kb * AST + p20 + r4];
            a[0][1] = smu[OFF_A2 + kb * AST + p20 + r4 + 8];
            a[0][2] = smu[OFF_A2 + (kb + 4) * AST + p20 + r4];
            a[0][3] = smu[OFF_A2 + (kb + 4) * AST + p20 + r4 + 8];
            // mt1: j rows 16+r4 (clamped), 24+r4 (all clamp to 19 = pad col)
            int j2 = (16 + r4 < 19) ? 16 + r4 : 19;
            a[1][0] = smu[OFF_A2 + kb * AST + p20 + j2];
            a[1][1] = smu[OFF_A2 + kb * AST + p20 + 19];
            a[1][2] = smu[OFF_A2 + (kb + 4) * AST + p20 + j2];
            a[1][3] = smu[OFF_A2 + (kb + 4) * AST + p20 + 19];
            u32 b[3][2];
            #pragma unroll
            for (int nt = 0; nt < 3; ++nt) {
                int kcol = nt * 8 + r4;
                b[nt][0] = smu[OFF_A1 + kb * AST + p20 + kcol];
                b[nt][1] = smu[OFF_A1 + (kb + 4) * AST + p20 + kcol];
            }
            #pragma unroll
            for (int mt = 0; mt < 2; ++mt)
                #pragma unroll
                for (int nt = 0; nt < 3; ++nt)
                    mma_tf32(d[mt][nt], a[mt], b[nt]);
        }
        float* ltp = &sm[OFF_LT + w * LTP];
        #pragma unroll
        for (int mt = 0; mt < 2; ++mt)
            #pragma unroll
            for (int nt = 0; nt < 3; ++nt) {
                int col = nt * 8 + l4 * 2;
                int row = mt * 16 + r4;
                if (row < J_) {
                    if (col < J_)     ltp[row * LTS + col]     = d[mt][nt][0];
                    if (col + 1 < J_) ltp[row * LTS + col + 1] = d[mt][nt][1];
                }
                if (row + 8 < J_) {
                    if (col < J_)     ltp[(row + 8) * LTS + col]     = d[mt][nt][2];
                    if (col + 1 < J_) ltp[(row + 8) * LTS + col + 1] = d[mt][nt][3];
                }
            }
    } else {
        for (int u = (w - 8) * 32 + lane; u < 160; u += 64) {
            float a = 0.f;
            #pragma unroll 8
            for (int b = 0; b < 64; ++b)
                a += sm[OFF_V + b] * sm[OFF_A2 + b * AST + u];
            sm[OFF_VH + u] = a;
        }
    }
    __syncthreads();

    // ===== softmax over k per (p, j); store att as tf32; zero k-pads =====
    if (tid < 152) {
        int p = tid / J_, j = tid % J_;
        int lb = OFF_LT + p * LTP + j * LTS;
        float l[J_];
        float mx = -1e30f;
        #pragma unroll
        for (int k = 0; k < J_; ++k) {
            l[k] = sm[lb + k] + sm[OFF_VH + p * 20 + k];
            mx = fmaxf(mx, l[k]);
        }
        float sum = 0.f;
        #pragma unroll
        for (int k = 0; k < J_; ++k) { l[k] = __expf(l[k] - mx); sum += l[k]; }
        float inv = 1.f / sum;
        #pragma unroll
        for (int k = 0; k < J_; ++k) smu[lb + k] = f2tf(l[k] * inv);
        #pragma unroll
        for (int k = J_; k < LTS; ++k) sm[lb + k] = 0.f;
    }
    __syncthreads();

    // ===== AGG (mma): A[c][j*8+p] = sum_k H[c][p20+k] att[p][j][k] -> A1 =====
    for (int job = w; job < 16; job += 10) {
        int p = job >> 1, mh = job & 1;
        int p20 = p * 20;
        float d[2][3][4];
        #pragma unroll
        for (int mt = 0; mt < 2; ++mt)
            #pragma unroll
            for (int nt = 0; nt < 3; ++nt)
                #pragma unroll
                for (int e = 0; e < 4; ++e) d[mt][nt][e] = 0.f;
        #pragma unroll
        for (int ks = 0; ks < 3; ++ks) {
            int kb = ks * 8 + l4;
            u32 a[2][4];
            #pragma unroll
            for (int mt = 0; mt < 2; ++mt) {
                int c = (mh * 2 + mt) * 16 + r4;
                a[mt][0] = smu[OFF_A2 + c * AST + p20 + kb];
                a[mt][1] = smu[OFF_A2 + (c + 8) * AST + p20 + kb];
                a[mt][2] = smu[OFF_A2 + c * AST + p20 + kb + 4];
                a[mt][3] = smu[OFF_A2 + (c + 8) * AST + p20 + kb + 4];
            }
            u32 b[3][2];
            #pragma unroll
            for (int nt = 0; nt < 3; ++nt) {
                int jb = nt * 8 + r4; if (jb > 18) jb = 18;
                b[nt][0] = smu[OFF_LT + p * LTP + jb * LTS + kb];
                b[nt][1] = smu[OFF_LT + p * LTP + jb * LTS + kb + 4];
            }
            #pragma unroll
            for (int mt = 0; mt < 2; ++mt)
                #pragma unroll
                for (int nt = 0; nt < 3; ++nt)
                    mma_tf32(d[mt][nt], a[mt], b[nt]);
        }
        #pragma unroll
        for (int mt = 0; mt < 2; ++mt)
            #pragma unroll
            for (int nt = 0; nt < 3; ++nt) {
                int c = (mh * 2 + mt) * 16 + r4;
                int j = nt * 8 + l4 * 2;
                if (j < J_)     smu[OFF_A1 + c * AST + j * 8 + p]       = f2tf(d[mt][nt][0]);
                if (j + 1 < J_) smu[OFF_A1 + c * AST + (j + 1) * 8 + p] = f2tf(d[mt][nt][1]);
                if (j < J_)     smu[OFF_A1 + (c + 8) * AST + j * 8 + p]       = f2tf(d[mt][nt][2]);
                if (j + 1 < J_) smu[OFF_A1 + (c + 8) * AST + (j + 1) * 8 + p] = f2tf(d[mt][nt][3]);
            }
    }
    __syncthreads();

    // reload SWB = tf32(Wt)   (LT dead now)
    for (int q = tid; q < 1024; q += NTH) {
        float4 v = *(const float4*)&g_Wt[q * 4];
        int d = q >> 4, k4 = (q & 15) * 4;
        int base = OFF_SWB + d * WST + k4;
        smu[base]     = f2tf(v.x); smu[base + 1] = f2tf(v.y);
        smu[base + 2] = f2tf(v.z); smu[base + 3] = f2tf(v.w);
    }
    __syncthreads();

    // ================= OUT: Wt * AGG -> stage into A2 (f32) ==================
    mma_phase<0, 0, 0>(sm, OFF_A1, OFF_A2, 152, w, lane);
    __syncthreads();

    // ===== coalesced global store from A2[o][j*8+p] =====
    {
        int b   = pix0 / 2560;
        int ts0 = pix0 % 2560;
        for (int v = tid; v < 64 * 38; v += NTH) {
            int o = v / 38, rr = v % 38;
            int j = rr >> 1, pb = (rr & 1) * 4;
            float4 t = *(const float4*)&sm[OFF_A2 + o * AST + j * 8 + pb];
            *(float4*)&out[((size_t)((b * 64 + o) * J_ + j)) * 2560 + ts0 + pb] = t;
        }
    }
}

// ------------------------------ launcher --------------------------------------
extern "C" void kernel_launch(void* const* d_in, const int* in_sizes, int n_in,
                              void* d_out, int out_size) {
    const float* x     = (const float*)d_in[0];
    const float* gamma = (const float*)d_in[1];
    const float* beta  = (const float*)d_in[2];
    const float* w1    = (const float*)d_in[3];
    const float* b1    = (const float*)d_in[4];
    const float* w2    = (const float*)d_in[5];
    const float* b2    = (const float*)d_in[6];
    const float* ws1   = (const float*)d_in[7];
    const float* bs1   = (const float*)d_in[8];
    const float* ws2   = (const float*)d_in[9];
    // d_in[10] = bs2 (softmax-invariant), d_in[11] = W
    const float* W     = (const float*)d_in[11];
    float* out = (float*)d_out;

    cudaFuncSetAttribute(geo_gcn_main_kernel,
                         cudaFuncAttributeMaxDynamicSharedMemorySize, SMEM_BYTES);

    bn_stats_kernel<<<NCH / 8, 256>>>(x, gamma, beta);
    setup_kernel<<<16, 256>>>(w1, ws1, bs1, ws2, W);
    xn_kernel<<<B_ * 32, 256>>>(x);
    geo_gcn_main_kernel<<<NPIX / PPB, NTH, SMEM_BYTES>>>(b1, b2, w2, out);
}

// round 12
// speedup vs baseline: 2.4993x; 1.0020x over previous
#include <cuda_runtime.h>
#include <cuda_bf16.h>
#include <math.h>

// Problem constants
#define B_  16
#define C_  4
#define J_  19
#define T_  256
#define S_  10
#define NCH (C_*J_*T_)          // 19456 BN channels
#define NPIX (B_*T_*S_)         // 40960 pixels
#define EPSV 1e-5f

#define PPB 8                   // pixels per block
#define AST 168                 // activation stride (8*l4+r4 conflict-free)
#define WST 68                  // weight stride (4*r4+l4 conflict-free)
#define NTH 320
#define LTS 28                  // LT row stride
#define LTP (J_*LTS)            // 532 per-pixel LT stride

typedef unsigned long long u64;
typedef unsigned int u32;

// ---- f32x2 packed helpers (scalar phases) --------------------------------------
__device__ __forceinline__ u64 dup2(float a) {
    u64 r; asm("mov.b64 %0, {%1, %1};" : "=l"(r) : "f"(a)); return r;
}
__device__ __forceinline__ void upk2(u64 v, float& lo, float& hi) {
    asm("mov.b64 {%0, %1}, %2;" : "=f"(lo), "=f"(hi) : "l"(v));
}
__device__ __forceinline__ void fma2(u64& d, u64 a, u64 b) {
    asm("fma.rn.f32x2 %0, %1, %2, %0;" : "+l"(d) : "l"(a), "l"(b));
}
__device__ __forceinline__ void lds_v2u64(const float* p, u64& lo, u64& hi) {
    unsigned a = (unsigned)__cvta_generic_to_shared(p);
    asm("ld.shared.v2.u64 {%0, %1}, [%2];" : "=l"(lo), "=l"(hi) : "r"(a));
}
// ---- tf32 helpers ---------------------------------------------------------------
__device__ __forceinline__ u32 f2tf(float f) {
    u32 u; asm("cvt.rna.tf32.f32 %0, %1;" : "=r"(u) : "f"(f)); return u;
}
__device__ __forceinline__ void mma_tf32(float d[4], const u32 a[4], const u32 b[2]) {
    asm volatile(
        "mma.sync.aligned.m16n8k8.row.col.f32.tf32.tf32.f32 "
        "{%0,%1,%2,%3}, {%4,%5,%6,%7}, {%8,%9}, {%0,%1,%2,%3};\n"
        : "+f"(d[0]), "+f"(d[1]), "+f"(d[2]), "+f"(d[3])
        : "r"(a[0]), "r"(a[1]), "r"(a[2]), "r"(a[3]), "r"(b[0]), "r"(b[1]));
}

// ---------------- device scratch ----------------------------------------------
__device__ float g_bn_a[NCH + 256];   // +pad so t+1 overread is safe
__device__ float g_bn_b[NCH + 256];
__device__ float g_w1t[C_*64];        // w1t[c][d] (fp32, phase B)
__device__ u32   g_w2s[64*WST];       // tf32, strided: [d*68 + k]
__device__ u32   g_Ms [64*WST];       // tf32 M[a][b] at [a*68 + b]
__device__ u32   g_Wts[64*WST];       // tf32 Wt[o][c] at [o*68 + c]
__device__ float g_v[64];

// ---------------- kernel 1: BN statistics ---------------------------------------
__global__ void bn_stats_kernel(const float* __restrict__ x,
                                const float* __restrict__ gamma,
                                const float* __restrict__ beta) {
    int ch = blockIdx.x * 8 + (threadIdx.x >> 5);
    if (ch >= NCH) return;
    int lane = threadIdx.x & 31;
    float s = 0.f, ss = 0.f;
    for (int e = lane; e < B_ * S_; e += 32) {
        int b = e / S_, si = e % S_;
        float v = x[(b * NCH + ch) * S_ + si];
        s += v; ss += v * v;
    }
    #pragma unroll
    for (int off = 16; off; off >>= 1) {
        s  += __shfl_xor_sync(0xffffffffu, s,  off);
        ss += __shfl_xor_sync(0xffffffffu, ss, off);
    }
    if (lane == 0) {
        const float inv_n = 1.f / (float)(B_ * S_);
        float mean = s * inv_n;
        float var  = ss * inv_n - mean * mean;
        float a = gamma[ch] * rsqrtf(var + EPSV);
        g_bn_a[ch] = a;
        g_bn_b[ch] = beta[ch] - mean * a;
    }
}

// ---------------- kernel 2: precompute tf32-strided weights, v, w1t --------------
__global__ void setup_kernel(const float* __restrict__ w1,
                             const float* __restrict__ ws1,
                             const float* __restrict__ bs1,
                             const float* __restrict__ ws2,
                             const float* __restrict__ w2,
                             const float* __restrict__ W) {
    int idx = blockIdx.x * blockDim.x + threadIdx.x;
    if (idx < 4096) {
        int a = idx >> 6, b = idx & 63;
        float acc = 0.f;
        #pragma unroll 4
        for (int s = 0; s < 128; ++s)
            acc += ws1[s * 64 + a] * ws2[s * 64 + b];
        g_Ms [a * WST + b] = f2tf(acc);
        g_w2s[a * WST + b] = f2tf(w2[idx]);           // w2[d][k], row-major
        g_Wts[a * WST + b] = f2tf(W[b * 64 + a]);     // Wt[o][c] = W[c][o]
    }
    if (idx < C_ * 64) g_w1t[idx] = w1[(idx & 63) * C_ + (idx >> 6)];
    if (idx < 64) {
        float acc = 0.f;
        #pragma unroll 4
        for (int s = 0; s < 128; ++s)
            acc += ws2[s * 64 + idx] * bs1[s];
        g_v[idx] = acc;
        #pragma unroll
        for (int e = 64; e < WST; ++e) {   // zero row pads
            g_Ms [idx * WST + e] = 0;
            g_w2s[idx * WST + e] = 0;
            g_Wts[idx * WST + e] = 0;
        }
    }
    if (idx < 256) { g_bn_a[NCH + idx] = 0.f; g_bn_b[NCH + idx] = 0.f; }
}

// ---------------- smem layout (float offsets) ----------------------------------
#define OFF_W1T   0        // 256 (VH aliases after phase B)
#define OFF_B1    256
#define OFF_B2    320
#define OFF_V     384
#define OFF_SWB   448      // 64*68 = 4352, time-shared: w2 -> M -> LT -> Wt
#define OFF_A1    4800     // 64*168 = 10752 : h1 -> G -> AGG
#define OFF_A2    15552    // 64*168 = 10752 : XN -> H
#define SMEM_FLOATS 26304
#define SMEM_BYTES (SMEM_FLOATS * 4)   // 105,216 B -> 2 blocks/SM
#define OFF_XN    OFF_A2
#define OFF_LT    OFF_SWB               // 8*532 = 4256
#define OFF_VH    OFF_W1T               // 160 (W1T dead after phase B)
#define SWB_U4    (64*WST/4)            // 1088 uint4 per weight image

// ---- tf32 mma GEMM: D[64 x nCols] = A(SWB) * B(offB); warp = 2m x 4n tiles ------
template<int BIAS, int RELU, int CVT>
__device__ __forceinline__ void mma_phase(float* sm, int offB, int offD,
                                          int nLimit, int w, int lane) {
    u32* smu = (u32*)sm;
    const int r4 = lane >> 2, l4 = lane & 3;
    const int wm = (w >= 5) ? 1 : 0;
    const int wn = w - wm * 5;
    const int m0 = wm * 32;
    const int n0 = wn * 32;
    float d[2][4][4];
    #pragma unroll
    for (int mt = 0; mt < 2; ++mt) {
        float bz0 = 0.f, bz1 = 0.f;
        if (BIAS) {
            bz0 = sm[OFF_B2 + m0 + mt * 16 + r4];
            bz1 = sm[OFF_B2 + m0 + mt * 16 + 8 + r4];
        }
        #pragma unroll
        for (int nt = 0; nt < 4; ++nt) {
            d[mt][nt][0] = bz0; d[mt][nt][1] = bz0;
            d[mt][nt][2] = bz1; d[mt][nt][3] = bz1;
        }
    }
    #pragma unroll
    for (int k0 = 0; k0 < 64; k0 += 8) {
        u32 a[2][4];
        #pragma unroll
        for (int mt = 0; mt < 2; ++mt) {
            int base = OFF_SWB + (m0 + mt * 16 + r4) * WST + k0 + l4;
            a[mt][0] = smu[base];
            a[mt][1] = smu[base + 8 * WST];
            a[mt][2] = smu[base + 4];
            a[mt][3] = smu[base + 8 * WST + 4];
        }
        u32 b[4][2];
        #pragma unroll
        for (int nt = 0; nt < 4; ++nt) {
            int n = n0 + nt * 8;
            if (n < nLimit) {
                int base = offB + (k0 + l4) * AST + n + r4;
                b[nt][0] = smu[base];
                b[nt][1] = smu[base + 4 * AST];
            }
        }
        #pragma unroll
        for (int nt = 0; nt < 4; ++nt)
            if (n0 + nt * 8 < nLimit)
                #pragma unroll
                for (int mt = 0; mt < 2; ++mt)
                    mma_tf32(d[mt][nt], a[mt], b[nt]);
    }
    #pragma unroll
    for (int mt = 0; mt < 2; ++mt)
        #pragma unroll
        for (int nt = 0; nt < 4; ++nt) {
            int n = n0 + nt * 8;
            if (n < nLimit) {
                int col = n + l4 * 2;
                int row0 = m0 + mt * 16 + r4;
                float v0 = d[mt][nt][0], v1 = d[mt][nt][1];
                float v2 = d[mt][nt][2], v3 = d[mt][nt][3];
                if (RELU) {
                    v0 = fmaxf(v0, 0.f); v1 = fmaxf(v1, 0.f);
                    v2 = fmaxf(v2, 0.f); v3 = fmaxf(v3, 0.f);
                }
                if (CVT) {
                    *(uint2*)&smu[offD + row0 * AST + col] =
                        make_uint2(f2tf(v0), f2tf(v1));
                    *(uint2*)&smu[offD + (row0 + 8) * AST + col] =
                        make_uint2(f2tf(v2), f2tf(v3));
                } else {
                    *(float2*)&sm[offD + row0 * AST + col] = make_float2(v0, v1);
                    *(float2*)&sm[offD + (row0 + 8) * AST + col] = make_float2(v2, v3);
                }
            }
        }
}

__global__ __launch_bounds__(NTH, 2)
void geo_gcn_main_kernel(const float* __restrict__ x,
                         const float* __restrict__ b1g,
                         const float* __restrict__ b2g,
                         float* __restrict__ out) {
    extern __shared__ float sm[];
    u32* smu = (u32*)sm;
    const int tid = threadIdx.x;
    const int pix0 = blockIdx.x * PPB;
    const int w = tid >> 5, lane = tid & 31;
    const int r4 = lane >> 2, l4 = lane & 3;

    const int bb  = pix0 / 2560;
    const int ts0 = pix0 % 2560;

    // ---- prologue: SWB = w2s (linear uint4 copy); w1t/biases/v; fused BN+XN ----
    for (int q = tid; q < SWB_U4; q += NTH)
        *(uint4*)&smu[OFF_SWB + q * 4] = *(const uint4*)&g_w2s[q * 4];
    if (tid < 64) {
        *(float4*)&sm[OFF_W1T + tid * 4] = *(const float4*)&g_w1t[tid * 4];
        sm[OFF_B1 + tid] = b1g[tid];
        sm[OFF_B2 + tid] = b2g[tid];
        sm[OFF_V  + tid] = g_v[tid];
    }
    if (tid < 76) {
        // fused BN-apply: channel ch = tid, 8 contiguous ts pixels
        int ch = tid;
        int t0 = ts0 / 10, s0 = ts0 % 10;
        const float* xp = &x[((size_t)(bb * 76 + ch)) * 2560 + ts0];
        float4 v0 = *(const float4*)xp;
        float4 v1 = *(const float4*)(xp + 4);
        float a0 = g_bn_a[ch * 256 + t0];
        float bz0 = g_bn_b[ch * 256 + t0];
        float a1 = g_bn_a[ch * 256 + t0 + 1];   // padded arrays: safe overread
        float bz1 = g_bn_b[ch * 256 + t0 + 1];
        int c = ch / 19, j = ch % 19;
        float xv[8] = {v0.x, v0.y, v0.z, v0.w, v1.x, v1.y, v1.z, v1.w};
        #pragma unroll
        for (int p = 0; p < 8; ++p) {
            bool nx = (s0 + p >= 10);
            float val = xv[p] * (nx ? a1 : a0) + (nx ? bz1 : bz0);
            sm[OFF_XN + c * AST + p * 20 + j] = val;
        }
    } else if (tid >= 152 && tid < 160) {
        int pp = tid - 152;   // zero j=19 pad cols of XN
        #pragma unroll
        for (int c = 0; c < C_; ++c)
            sm[OFF_XN + c * AST + pp * 20 + 19] = 0.f;
    } else if (tid >= 160 && tid < 288) {
        // zero A2 pad cols 160..167 (NaN safety for mma n-overreach)
        int u = tid - 160;
        int row = u >> 1, colb = 160 + (u & 1) * 4;
        *(float4*)&sm[OFF_A2 + row * AST + colb] = make_float4(0.f, 0.f, 0.f, 0.f);
    }
    __syncthreads();

    // ================= Phase B: h1 = relu(W1 xn + b1) -> A1 (tf32) ==========
    {
        const int dg = tid / 40, cg = tid % 40;
        const int d0 = dg * 8, col0 = cg * 4;
        u64 acc[8][2];
        #pragma unroll
        for (int i = 0; i < 8; ++i) {
            u64 bv = dup2(sm[OFF_B1 + d0 + i]);
            acc[i][0] = bv; acc[i][1] = bv;
        }
        #pragma unroll
        for (int k = 0; k < C_; ++k) {
            float4 w0 = *(const float4*)&sm[OFF_W1T + k * 64 + d0];
            float4 w1 = *(const float4*)&sm[OFF_W1T + k * 64 + d0 + 4];
            u64 a01, a23;
            lds_v2u64(&sm[OFF_XN + k * AST + col0], a01, a23);
            #pragma unroll
            for (int i = 0; i < 8; ++i) {
                u64 wd = dup2(i < 4 ? (&w0.x)[i] : (&w1.x)[i - 4]);
                fma2(acc[i][0], wd, a01);
                fma2(acc[i][1], wd, a23);
            }
        }
        #pragma unroll
        for (int i = 0; i < 8; ++i) {
            float v0, v1, v2, v3;
            upk2(acc[i][0], v0, v1); upk2(acc[i][1], v2, v3);
            *(uint4*)&smu[OFF_A1 + (d0 + i) * AST + col0] =
                make_uint4(f2tf(fmaxf(v0, 0.f)), f2tf(fmaxf(v1, 0.f)),
                           f2tf(fmaxf(v2, 0.f)), f2tf(fmaxf(v3, 0.f)));
        }
    }
    __syncthreads();

    // ================= Phase C: H = relu(w2 h1 + b2) -> A2 (tf32) ===========
    mma_phase<1, 1, 1>(sm, OFF_A1, OFF_A2, 160, w, lane);
    __syncthreads();
    // reload SWB = Ms (linear uint4 copy)
    for (int q = tid; q < SWB_U4; q += NTH)
        *(uint4*)&smu[OFF_SWB + q * 4] = *(const uint4*)&g_Ms[q * 4];
    __syncthreads();

    // ================= Phase D: G = M H -> A1 (tf32) =========================
    mma_phase<0, 0, 1>(sm, OFF_A2, OFF_A1, 160, w, lane);
    __syncthreads();

    // ===== Phase F (mma): logits L[p][j][k] = sum_a H[a][j] G[a][k] -> LT =====
    if (w < 8) {
        const int p20 = w * 20;
        float d[2][3][4];
        #pragma unroll
        for (int mt = 0; mt < 2; ++mt)
            #pragma unroll
            for (int nt = 0; nt < 3; ++nt)
                #pragma unroll
                for (int e = 0; e < 4; ++e) d[mt][nt][e] = 0.f;
        #pragma unroll
        for (int ks = 0; ks < 8; ++ks) {
            int kb = ks * 8 + l4;
            u32 a[2][4];
            a[0][0] = smu[OFF_A2 + kb * AST + p20 + r4];
            a[0][1] = smu[OFF_A2 + kb * AST + p20 + r4 + 8];
            a[0][2] = smu[OFF_A2 + (kb + 4) * AST + p20 + r4];
            a[0][3] = smu[OFF_A2 + (kb + 4) * AST + p20 + r4 + 8];
            int j2 = (16 + r4 < 19) ? 16 + r4 : 19;
            a[1][0] = smu[OFF_A2 + kb * AST + p20 + j2];
            a[1][1] = smu[OFF_A2 + kb * AST + p20 + 19];
            a[1][2] = smu[OFF_A2 + (kb + 4) * AST + p20 + j2];
            a[1][3] = smu[OFF_A2 + (kb + 4) * AST + p20 + 19];
            u32 b[3][2];
            #pragma unroll
            for (int nt = 0; nt < 3; ++nt) {
                int kcol = nt * 8 + r4;
                b[nt][0] = smu[OFF_A1 + kb * AST + p20 + kcol];
                b[nt][1] = smu[OFF_A1 + (kb + 4) * AST + p20 + kcol];
            }
            #pragma unroll
            for (int mt = 0; mt < 2; ++mt)
                #pragma unroll
                for (int nt = 0; nt < 3; ++nt)
                    mma_tf32(d[mt][nt], a[mt], b[nt]);
        }
        float* ltp = &sm[OFF_LT + w * LTP];
        #pragma unroll
        for (int mt = 0; mt < 2; ++mt)
            #pragma unroll
            for (int nt = 0; nt < 3; ++nt) {
                int col = nt * 8 + l4 * 2;
                int row = mt * 16 + r4;
                if (row < J_) {
                    if (col < J_)     ltp[row * LTS + col]     = d[mt][nt][0];
                    if (col + 1 < J_) ltp[row * LTS + col + 1] = d[mt][nt][1];
                }
                if (row + 8 < J_) {
                    if (col < J_)     ltp[(row + 8) * LTS + col]     = d[mt][nt][2];
                    if (col + 1 < J_) ltp[(row + 8) * LTS + col + 1] = d[mt][nt][3];
                }
            }
    } else {
        for (int u = (w - 8) * 32 + lane; u < 160; u += 64) {
            float a = 0.f;
            #pragma unroll 8
            for (int b = 0; b < 64; ++b)
                a += sm[OFF_V + b] * sm[OFF_A2 + b * AST + u];
            sm[OFF_VH + u] = a;
        }
    }
    __syncthreads();

    // ===== softmax over k per (p, j); store att tf32; zero k-pads =====
    if (tid < 152) {
        int p = tid / J_, j = tid % J_;
        int lb = OFF_LT + p * LTP + j * LTS;
        float l[J_];
        float mx = -1e30f;
        #pragma unroll
        for (int k = 0; k < J_; ++k) {
            l[k] = sm[lb + k] + sm[OFF_VH + p * 20 + k];
            mx = fmaxf(mx, l[k]);
        }
        float sum = 0.f;
        #pragma unroll
        for (int k = 0; k < J_; ++k) { l[k] = __expf(l[k] - mx); sum += l[k]; }
        float inv = 1.f / sum;
        #pragma unroll
        for (int k = 0; k < J_; ++k) smu[lb + k] = f2tf(l[k] * inv);
        #pragma unroll
        for (int k = J_; k < LTS; ++k) sm[lb + k] = 0.f;
    }
    __syncthreads();

    // ===== AGG (mma): A[c][j*8+p] = sum_k H[c][p20+k] att[p][j][k] -> A1 =====
    for (int job = w; job < 16; job += 10) {
        int p = job >> 1, mh = job & 1;
        int p20 = p * 20;
        float d[2][3][4];
        #pragma unroll
        for (int mt = 0; mt < 2; ++mt)
            #pragma unroll
            for (int nt = 0; nt < 3; ++nt)
                #pragma unroll
                for (int e = 0; e < 4; ++e) d[mt][nt][e] = 0.f;
        #pragma unroll
        for (int ks = 0; ks < 3; ++ks) {
            int kb = ks * 8 + l4;
            u32 a[2][4];
            #pragma unroll
            for (int mt = 0; mt < 2; ++mt) {
                int c = (mh * 2 + mt) * 16 + r4;
                a[mt][0] = smu[OFF_A2 + c * AST + p20 + kb];
                a[mt][1] = smu[OFF_A2 + (c + 8) * AST + p20 + kb];
                a[mt][2] = smu[OFF_A2 + c * AST + p20 + kb + 4];
                a[mt][3] = smu[OFF_A2 + (c + 8) * AST + p20 + kb + 4];
            }
            u32 b[3][2];
            #pragma unroll
            for (int nt = 0; nt < 3; ++nt) {
                int jb = nt * 8 + r4; if (jb > 18) jb = 18;
                b[nt][0] = smu[OFF_LT + p * LTP + jb * LTS + kb];
                b[nt][1] = smu[OFF_LT + p * LTP + jb * LTS + kb + 4];
            }
            #pragma unroll
            for (int mt = 0; mt < 2; ++mt)
                #pragma unroll
                for (int nt = 0; nt < 3; ++nt)
                    mma_tf32(d[mt][nt], a[mt], b[nt]);
        }
        #pragma unroll
        for (int mt = 0; mt < 2; ++mt)
            #pragma unroll
            for (int nt = 0; nt < 3; ++nt) {
                int c = (mh * 2 + mt) * 16 + r4;
                int j = nt * 8 + l4 * 2;
                if (j < J_)     smu[OFF_A1 + c * AST + j * 8 + p]       = f2tf(d[mt][nt][0]);
                if (j + 1 < J_) smu[OFF_A1 + c * AST + (j + 1) * 8 + p] = f2tf(d[mt][nt][1]);
                if (j < J_)     smu[OFF_A1 + (c + 8) * AST + j * 8 + p]       = f2tf(d[mt][nt][2]);
                if (j + 1 < J_) smu[OFF_A1 + (c + 8) * AST + (j + 1) * 8 + p] = f2tf(d[mt][nt][3]);
            }
    }
    __syncthreads();

    // reload SWB = Wts (linear uint4 copy; LT dead now)
    for (int q = tid; q < SWB_U4; q += NTH)
        *(uint4*)&smu[OFF_SWB + q * 4] = *(const uint4*)&g_Wts[q * 4];
    __syncthreads();

    // ================= OUT: Wt * AGG -> stage into A2 (f32) ==================
    mma_phase<0, 0, 0>(sm, OFF_A1, OFF_A2, 152, w, lane);
    __syncthreads();

    // ===== coalesced global store from A2[o][j*8+p] =====
    for (int v = tid; v < 64 * 38; v += NTH) {
        int o = v / 38, rr = v % 38;
        int j = rr >> 1, pb = (rr & 1) * 4;
        float4 t = *(const float4*)&sm[OFF_A2 + o * AST + j * 8 + pb];
        *(float4*)&out[((size_t)((bb * 64 + o) * J_ + j)) * 2560 + ts0 + pb] = t;
    }
}

// ------------------------------ launcher --------------------------------------
extern "C" void kernel_launch(void* const* d_in, const int* in_sizes, int n_in,
                              void* d_out, int out_size) {
    const float* x     = (const float*)d_in[0];
    const float* gamma = (const float*)d_in[1];
    const float* beta  = (const float*)d_in[2];
    const float* w1    = (const float*)d_in[3];
    const float* b1    = (const float*)d_in[4];
    const float* w2    = (const float*)d_in[5];
    const float* b2    = (const float*)d_in[6];
    const float* ws1   = (const float*)d_in[7];
    const float* bs1   = (const float*)d_in[8];
    const float* ws2   = (const float*)d_in[9];
    // d_in[10] = bs2 (softmax-invariant), d_in[11] = W
    const float* W     = (const float*)d_in[11];
    float* out = (float*)d_out;

    cudaFuncSetAttribute(geo_gcn_main_kernel,
                         cudaFuncAttributeMaxDynamicSharedMemorySize, SMEM_BYTES);

    bn_stats_kernel<<<NCH / 8, 256>>>(x, gamma, beta);
    setup_kernel<<<16, 256>>>(w1, ws1, bs1, ws2, w2, W);
    geo_gcn_main_kernel<<<NPIX / PPB, NTH, SMEM_BYTES>>>(x, b1, b2, out);
}

// round 14
// speedup vs baseline: 2.8380x; 1.1355x over previous
#include <cuda_runtime.h>
#include <cuda_bf16.h>
#include <math.h>

// Problem constants
#define B_  16
#define C_  4
#define J_  19
#define T_  256
#define S_  10
#define NCH (C_*J_*T_)          // 19456 BN channels
#define NPIX (B_*T_*S_)         // 40960 pixels
#define EPSV 1e-5f

#define PPB 8                   // pixels per block
#define AST 168                 // activation stride (8*l4+r4 conflict-free)
#define WST 68                  // weight stride (4*r4+l4 conflict-free)
#define NTH 320
#define LTS 28                  // LT row stride
#define LTP (J_*LTS)            // 532 per-pixel LT stride

typedef unsigned long long u64;
typedef unsigned int u32;

// ---- f32x2 packed helpers (scalar phases) --------------------------------------
__device__ __forceinline__ u64 dup2(float a) {
    u64 r; asm("mov.b64 %0, {%1, %1};" : "=l"(r) : "f"(a)); return r;
}
__device__ __forceinline__ void upk2(u64 v, float& lo, float& hi) {
    asm("mov.b64 {%0, %1}, %2;" : "=f"(lo), "=f"(hi) : "l"(v));
}
__device__ __forceinline__ void fma2(u64& d, u64 a, u64 b) {
    asm("fma.rn.f32x2 %0, %1, %2, %0;" : "+l"(d) : "l"(a), "l"(b));
}
__device__ __forceinline__ void lds_v2u64(const float* p, u64& lo, u64& hi) {
    unsigned a = (unsigned)__cvta_generic_to_shared(p);
    asm("ld.shared.v2.u64 {%0, %1}, [%2];" : "=l"(lo), "=l"(hi) : "r"(a));
}
// ---- tf32 helpers ---------------------------------------------------------------
__device__ __forceinline__ u32 f2tf(float f) {
    u32 u; asm("cvt.rna.tf32.f32 %0, %1;" : "=r"(u) : "f"(f)); return u;
}
__device__ __forceinline__ void mma_tf32(float d[4], const u32 a[4], const u32 b[2]) {
    asm volatile(
        "mma.sync.aligned.m16n8k8.row.col.f32.tf32.tf32.f32 "
        "{%0,%1,%2,%3}, {%4,%5,%6,%7}, {%8,%9}, {%0,%1,%2,%3};\n"
        : "+f"(d[0]), "+f"(d[1]), "+f"(d[2]), "+f"(d[3])
        : "r"(a[0]), "r"(a[1]), "r"(a[2]), "r"(a[3]), "r"(b[0]), "r"(b[1]));
}

// ---------------- device scratch ----------------------------------------------
__device__ float g_bn_a[NCH + 256];   // +pad so t+1 overread is safe
__device__ float g_bn_b[NCH + 256];
__device__ float g_w1t[C_*64];        // w1t[c][d] (fp32, phase B)
__device__ u32   g_w2s[64*WST];       // tf32, strided: [d*68 + k]
__device__ u32   g_Ms [64*WST];       // tf32 M[a][b] at [a*68 + b]
__device__ u32   g_Wts[64*WST];       // tf32 Wt[o][c] at [o*68 + c]
__device__ float g_v[64];

// ---------------- kernel 1: BN statistics ---------------------------------------
__global__ void bn_stats_kernel(const float* __restrict__ x,
                                const float* __restrict__ gamma,
                                const float* __restrict__ beta) {
    int ch = blockIdx.x * 8 + (threadIdx.x >> 5);
    if (ch >= NCH) return;
    int lane = threadIdx.x & 31;
    float s = 0.f, ss = 0.f;
    for (int e = lane; e < B_ * S_; e += 32) {
        int b = e / S_, si = e % S_;
        float v = x[(b * NCH + ch) * S_ + si];
        s += v; ss += v * v;
    }
    #pragma unroll
    for (int off = 16; off; off >>= 1) {
        s  += __shfl_xor_sync(0xffffffffu, s,  off);
        ss += __shfl_xor_sync(0xffffffffu, ss, off);
    }
    if (lane == 0) {
        const float inv_n = 1.f / (float)(B_ * S_);
        float mean = s * inv_n;
        float var  = ss * inv_n - mean * mean;
        float a = gamma[ch] * rsqrtf(var + EPSV);
        g_bn_a[ch] = a;
        g_bn_b[ch] = beta[ch] - mean * a;
    }
}

// ---------------- kernel 2: precompute tf32-strided weights, v, w1t --------------
__global__ void setup_kernel(const float* __restrict__ w1,
                             const float* __restrict__ ws1,
                             const float* __restrict__ bs1,
                             const float* __restrict__ ws2,
                             const float* __restrict__ w2,
                             const float* __restrict__ W) {
    int idx = blockIdx.x * blockDim.x + threadIdx.x;
    if (idx < 4096) {
        int a = idx >> 6, b = idx & 63;
        float acc = 0.f;
        #pragma unroll 4
        for (int s = 0; s < 128; ++s)
            acc += ws1[s * 64 + a] * ws2[s * 64 + b];
        g_Ms [a * WST + b] = f2tf(acc);
        g_w2s[a * WST + b] = f2tf(w2[idx]);
        g_Wts[a * WST + b] = f2tf(W[b * 64 + a]);
    }
    if (idx < C_ * 64) g_w1t[idx] = w1[(idx & 63) * C_ + (idx >> 6)];
    if (idx < 64) {
        float acc = 0.f;
        #pragma unroll 4
        for (int s = 0; s < 128; ++s)
            acc += ws2[s * 64 + idx] * bs1[s];
        g_v[idx] = acc;
        #pragma unroll
        for (int e = 64; e < WST; ++e) {
            g_Ms [idx * WST + e] = 0;
            g_w2s[idx * WST + e] = 0;
            g_Wts[idx * WST + e] = 0;
        }
    }
    if (idx < 256) { g_bn_a[NCH + idx] = 0.f; g_bn_b[NCH + idx] = 0.f; }
}

// ---------------- smem layout (float offsets) ----------------------------------
#define OFF_W1T   0        // 256 (VH aliases after phase B)
#define OFF_B1    256
#define OFF_B2    320
#define OFF_V     384
#define OFF_SWB   448      // 64*68 = 4352, time-shared: w2 -> M -> LT -> Wt
#define OFF_A1    4800     // 64*168 = 10752 : h1 -> G -> AGG(pixel-local)
#define OFF_A2    15552    // 64*168 = 10752 : XN -> H -> OUT stage
#define SMEM_FLOATS 26304
#define SMEM_BYTES (SMEM_FLOATS * 4)   // 105,216 B -> 2 blocks/SM
#define OFF_XN    OFF_A2
#define OFF_LT    OFF_SWB               // 8*532 = 4256
#define OFF_VH    OFF_W1T               // 160 (W1T dead after phase B)
#define SWB_U4    (64*WST/4)            // 1088 uint4 per weight image

// ---- tf32 mma GEMM (10 warps): D[64 x 160] = A(SWB) * B(offB); 2m x 4n ---------
template<int BIAS, int RELU, int CVT>
__device__ __forceinline__ void mma_phase(float* sm, int offB, int offD,
                                          int w, int lane) {
    u32* smu = (u32*)sm;
    const int r4 = lane >> 2, l4 = lane & 3;
    const int wm = (w >= 5) ? 1 : 0;
    const int wn = w - wm * 5;
    const int m0 = wm * 32;
    const int n0 = wn * 32;
    float d[2][4][4];
    #pragma unroll
    for (int mt = 0; mt < 2; ++mt) {
        float bz0 = 0.f, bz1 = 0.f;
        if (BIAS) {
            bz0 = sm[OFF_B2 + m0 + mt * 16 + r4];
            bz1 = sm[OFF_B2 + m0 + mt * 16 + 8 + r4];
        }
        #pragma unroll
        for (int nt = 0; nt < 4; ++nt) {
            d[mt][nt][0] = bz0; d[mt][nt][1] = bz0;
            d[mt][nt][2] = bz1; d[mt][nt][3] = bz1;
        }
    }
    #pragma unroll
    for (int k0 = 0; k0 < 64; k0 += 8) {
        u32 a[2][4];
        #pragma unroll
        for (int mt = 0; mt < 2; ++mt) {
            int base = OFF_SWB + (m0 + mt * 16 + r4) * WST + k0 + l4;
            a[mt][0] = smu[base];
            a[mt][1] = smu[base + 8 * WST];
            a[mt][2] = smu[base + 4];
            a[mt][3] = smu[base + 8 * WST + 4];
        }
        u32 b[4][2];
        #pragma unroll
        for (int nt = 0; nt < 4; ++nt) {
            int base = offB + (k0 + l4) * AST + n0 + nt * 8 + r4;
            b[nt][0] = smu[base];
            b[nt][1] = smu[base + 4 * AST];
        }
        #pragma unroll
        for (int nt = 0; nt < 4; ++nt)
            #pragma unroll
            for (int mt = 0; mt < 2; ++mt)
                mma_tf32(d[mt][nt], a[mt], b[nt]);
    }
    #pragma unroll
    for (int mt = 0; mt < 2; ++mt)
        #pragma unroll
        for (int nt = 0; nt < 4; ++nt) {
            int col = n0 + nt * 8 + l4 * 2;
            int row0 = m0 + mt * 16 + r4;
            float v0 = d[mt][nt][0], v1 = d[mt][nt][1];
            float v2 = d[mt][nt][2], v3 = d[mt][nt][3];
            if (RELU) {
                v0 = fmaxf(v0, 0.f); v1 = fmaxf(v1, 0.f);
                v2 = fmaxf(v2, 0.f); v3 = fmaxf(v3, 0.f);
            }
            if (CVT) {
                *(uint2*)&smu[offD + row0 * AST + col] =
                    make_uint2(f2tf(v0), f2tf(v1));
                *(uint2*)&smu[offD + (row0 + 8) * AST + col] =
                    make_uint2(f2tf(v2), f2tf(v3));
            } else {
                *(float2*)&sm[offD + row0 * AST + col] = make_float2(v0, v1);
                *(float2*)&sm[offD + (row0 + 8) * AST + col] = make_float2(v2, v3);
            }
        }
}

__global__ __launch_bounds__(NTH, 2)
void geo_gcn_main_kernel(const float* __restrict__ x,
                         const float* __restrict__ b1g,
                         const float* __restrict__ b2g,
                         float* __restrict__ out) {
    extern __shared__ float sm[];
    u32* smu = (u32*)sm;
    const int tid = threadIdx.x;
    const int pix0 = blockIdx.x * PPB;
    const int w = tid >> 5, lane = tid & 31;
    const int r4 = lane >> 2, l4 = lane & 3;

    const int bb  = pix0 / 2560;
    const int ts0 = pix0 % 2560;

    // ---- prologue: SWB = w2s; w1t/biases/v; fused BN+XN; zero A2 pads ----
    for (int q = tid; q < SWB_U4; q += NTH)
        *(uint4*)&smu[OFF_SWB + q * 4] = *(const uint4*)&g_w2s[q * 4];
    if (tid < 64) {
        *(float4*)&sm[OFF_W1T + tid * 4] = *(const float4*)&g_w1t[tid * 4];
        sm[OFF_B1 + tid] = b1g[tid];
        sm[OFF_B2 + tid] = b2g[tid];
        sm[OFF_V  + tid] = g_v[tid];
    }
    if (tid < 76) {
        int ch = tid;
        int t0 = ts0 / 10, s0 = ts0 % 10;
        const float* xp = &x[((size_t)(bb * 76 + ch)) * 2560 + ts0];
        float4 v0 = *(const float4*)xp;
        float4 v1 = *(const float4*)(xp + 4);
        float a0 = g_bn_a[ch * 256 + t0];
        float bz0 = g_bn_b[ch * 256 + t0];
        float a1 = g_bn_a[ch * 256 + t0 + 1];
        float bz1 = g_bn_b[ch * 256 + t0 + 1];
        int c = ch / 19, j = ch % 19;
        float xv[8] = {v0.x, v0.y, v0.z, v0.w, v1.x, v1.y, v1.z, v1.w};
        #pragma unroll
        for (int p = 0; p < 8; ++p) {
            bool nx = (s0 + p >= 10);
            float val = xv[p] * (nx ? a1 : a0) + (nx ? bz1 : bz0);
            sm[OFF_XN + c * AST + p * 20 + j] = val;
        }
    } else if (tid >= 152 && tid < 160) {
        int pp = tid - 152;
        #pragma unroll
        for (int c = 0; c < C_; ++c)
            sm[OFF_XN + c * AST + pp * 20 + 19] = 0.f;
    } else if (tid >= 160 && tid < 288) {
        int u = tid - 160;
        int row = u >> 1, colb = 160 + (u & 1) * 4;
        *(float4*)&sm[OFF_A2 + row * AST + colb] = make_float4(0.f, 0.f, 0.f, 0.f);
    }
    __syncthreads();

    // ================= Phase B: h1 = relu(W1 xn + b1) -> A1 (tf32) ==========
    {
        const int dg = tid / 40, cg = tid % 40;
        const int d0 = dg * 8, col0 = cg * 4;
        u64 acc[8][2];
        #pragma unroll
        for (int i = 0; i < 8; ++i) {
            u64 bv = dup2(sm[OFF_B1 + d0 + i]);
            acc[i][0] = bv; acc[i][1] = bv;
        }
        #pragma unroll
        for (int k = 0; k < C_; ++k) {
            float4 w0 = *(const float4*)&sm[OFF_W1T + k * 64 + d0];
            float4 w1 = *(const float4*)&sm[OFF_W1T + k * 64 + d0 + 4];
            u64 a01, a23;
            lds_v2u64(&sm[OFF_XN + k * AST + col0], a01, a23);
            #pragma unroll
            for (int i = 0; i < 8; ++i) {
                u64 wd = dup2(i < 4 ? (&w0.x)[i] : (&w1.x)[i - 4]);
                fma2(acc[i][0], wd, a01);
                fma2(acc[i][1], wd, a23);
            }
        }
        #pragma unroll
        for (int i = 0; i < 8; ++i) {
            float v0, v1, v2, v3;
            upk2(acc[i][0], v0, v1); upk2(acc[i][1], v2, v3);
            *(uint4*)&smu[OFF_A1 + (d0 + i) * AST + col0] =
                make_uint4(f2tf(fmaxf(v0, 0.f)), f2tf(fmaxf(v1, 0.f)),
                           f2tf(fmaxf(v2, 0.f)), f2tf(fmaxf(v3, 0.f)));
        }
    }
    __syncthreads();

    // ================= Phase C: H = relu(w2 h1 + b2) -> A2 (tf32) ===========
    mma_phase<1, 1, 1>(sm, OFF_A1, OFF_A2, w, lane);
    __syncthreads();
    // reload SWB = Ms
    for (int q = tid; q < SWB_U4; q += NTH)
        *(uint4*)&smu[OFF_SWB + q * 4] = *(const uint4*)&g_Ms[q * 4];
    __syncthreads();

    // ========= Phase D (8 warps): G = M H -> A1 (tf32);  warps 8,9: vh ========
    if (w < 8) {
        const int wm = w & 1, wn = w >> 1;
        const int m0 = wm * 32, n0 = wn * 40;
        float d[2][5][4];
        #pragma unroll
        for (int mt = 0; mt < 2; ++mt)
            #pragma unroll
            for (int nt = 0; nt < 5; ++nt)
                #pragma unroll
                for (int e = 0; e < 4; ++e) d[mt][nt][e] = 0.f;
        #pragma unroll
        for (int k0 = 0; k0 < 64; k0 += 8) {
            u32 a[2][4];
            #pragma unroll
            for (int mt = 0; mt < 2; ++mt) {
                int base = OFF_SWB + (m0 + mt * 16 + r4) * WST + k0 + l4;
                a[mt][0] = smu[base];
                a[mt][1] = smu[base + 8 * WST];
                a[mt][2] = smu[base + 4];
                a[mt][3] = smu[base + 8 * WST + 4];
            }
            u32 b[5][2];
            #pragma unroll
            for (int nt = 0; nt < 5; ++nt) {
                int base = OFF_A2 + (k0 + l4) * AST + n0 + nt * 8 + r4;
                b[nt][0] = smu[base];
                b[nt][1] = smu[base + 4 * AST];
            }
            #pragma unroll
            for (int nt = 0; nt < 5; ++nt)
                #pragma unroll
                for (int mt = 0; mt < 2; ++mt)
                    mma_tf32(d[mt][nt], a[mt], b[nt]);
        }
        #pragma unroll
        for (int mt = 0; mt < 2; ++mt)
            #pragma unroll
            for (int nt = 0; nt < 5; ++nt) {
                int col = n0 + nt * 8 + l4 * 2;
                int row0 = m0 + mt * 16 + r4;
                *(uint2*)&smu[OFF_A1 + row0 * AST + col] =
                    make_uint2(f2tf(d[mt][nt][0]), f2tf(d[mt][nt][1]));
                *(uint2*)&smu[OFF_A1 + (row0 + 8) * AST + col] =
                    make_uint2(f2tf(d[mt][nt][2]), f2tf(d[mt][nt][3]));
            }
    } else {
        for (int u = (w - 8) * 32 + lane; u < 160; u += 64) {
            float a = 0.f;
            #pragma unroll 8
            for (int b = 0; b < 64; ++b)
                a += sm[OFF_V + b] * sm[OFF_A2 + b * AST + u];
            sm[OFF_VH + u] = a;
        }
    }
    __syncthreads();

    // ===== FUSED per-warp: logits -> softmax -> AGG (warp p owns pixel p) =====
    if (w < 8) {
        const int p20 = w * 20;
        float* ltp = &sm[OFF_LT + w * LTP];
        // ---- logits: L[j][k] = sum_a H[a][j] G[a][k] ----
        {
            float d[2][3][4];
            #pragma unroll
            for (int mt = 0; mt < 2; ++mt)
                #pragma unroll
                for (int nt = 0; nt < 3; ++nt)
                    #pragma unroll
                    for (int e = 0; e < 4; ++e) d[mt][nt][e] = 0.f;
            #pragma unroll
            for (int ks = 0; ks < 8; ++ks) {
                int kb = ks * 8 + l4;
                u32 a[2][4];
                a[0][0] = smu[OFF_A2 + kb * AST + p20 + r4];
                a[0][1] = smu[OFF_A2 + kb * AST + p20 + r4 + 8];
                a[0][2] = smu[OFF_A2 + (kb + 4) * AST + p20 + r4];
                a[0][3] = smu[OFF_A2 + (kb + 4) * AST + p20 + r4 + 8];
                int j2 = (16 + r4 < 19) ? 16 + r4 : 19;
                a[1][0] = smu[OFF_A2 + kb * AST + p20 + j2];
                a[1][1] = smu[OFF_A2 + kb * AST + p20 + 19];
                a[1][2] = smu[OFF_A2 + (kb + 4) * AST + p20 + j2];
                a[1][3] = smu[OFF_A2 + (kb + 4) * AST + p20 + 19];
                u32 b[3][2];
                #pragma unroll
                for (int nt = 0; nt < 3; ++nt) {
                    int kcol = nt * 8 + r4;
                    b[nt][0] = smu[OFF_A1 + kb * AST + p20 + kcol];
                    b[nt][1] = smu[OFF_A1 + (kb + 4) * AST + p20 + kcol];
                }
                #pragma unroll
                for (int mt = 0; mt < 2; ++mt)
                    #pragma unroll
                    for (int nt = 0; nt < 3; ++nt)
                        mma_tf32(d[mt][nt], a[mt], b[nt]);
            }
            #pragma unroll
            for (int mt = 0; mt < 2; ++mt)
                #pragma unroll
                for (int nt = 0; nt < 3; ++nt) {
                    int col = nt * 8 + l4 * 2;
                    int row = mt * 16 + r4;
                    if (row < J_) {
                        if (col < J_)     ltp[row * LTS + col]     = d[mt][nt][0];
                        if (col + 1 < J_) ltp[row * LTS + col + 1] = d[mt][nt][1];
                    }
                    if (row + 8 < J_) {
                        if (col < J_)     ltp[(row + 8) * LTS + col]     = d[mt][nt][2];
                        if (col + 1 < J_) ltp[(row + 8) * LTS + col + 1] = d[mt][nt][3];
                    }
                }
        }
        __syncwarp();
        // ---- softmax over k, lane j < 19 ----
        if (lane < J_) {
            int lb = lane * LTS;
            float l[J_];
            float mx = -1e30f;
            #pragma unroll
            for (int k = 0; k < J_; ++k) {
                l[k] = ltp[lb + k] + sm[OFF_VH + p20 + k];
                mx = fmaxf(mx, l[k]);
            }
            float sum = 0.f;
            #pragma unroll
            for (int k = 0; k < J_; ++k) { l[k] = __expf(l[k] - mx); sum += l[k]; }
            float inv = 1.f / sum;
            #pragma unroll
            for (int k = 0; k < J_; ++k)
                ((u32*)ltp)[lb + k] = f2tf(l[k] * inv);
            #pragma unroll
            for (int k = J_; k < LTS; ++k) ltp[lb + k] = 0.f;
        }
        __syncwarp();
        // ---- AGG: A[c][p20+j] = sum_k H[c][p20+k] att[j][k]  (4m x 3n x 3k) ----
        {
            float d[4][3][4];
            #pragma unroll
            for (int mt = 0; mt < 4; ++mt)
                #pragma unroll
                for (int nt = 0; nt < 3; ++nt)
                    #pragma unroll
                    for (int e = 0; e < 4; ++e) d[mt][nt][e] = 0.f;
            #pragma unroll
            for (int ks = 0; ks < 3; ++ks) {
                int kb = ks * 8 + l4;
                u32 a[4][4];
                #pragma unroll
                for (int mt = 0; mt < 4; ++mt) {
                    int c = mt * 16 + r4;
                    a[mt][0] = smu[OFF_A2 + c * AST + p20 + kb];
                    a[mt][1] = smu[OFF_A2 + (c + 8) * AST + p20 + kb];
                    a[mt][2] = smu[OFF_A2 + c * AST + p20 + kb + 4];
                    a[mt][3] = smu[OFF_A2 + (c + 8) * AST + p20 + kb + 4];
                }
                u32 b[3][2];
                #pragma unroll
                for (int nt = 0; nt < 3; ++nt) {
                    int jb = nt * 8 + r4; if (jb > 18) jb = 18;
                    b[nt][0] = ((u32*)ltp)[jb * LTS + kb];
                    b[nt][1] = ((u32*)ltp)[jb * LTS + kb + 4];
                }
                #pragma unroll
                for (int mt = 0; mt < 4; ++mt)
                    #pragma unroll
                    for (int nt = 0; nt < 3; ++nt)
                        mma_tf32(d[mt][nt], a[mt], b[nt]);
            }
            #pragma unroll
            for (int mt = 0; mt < 4; ++mt)
                #pragma unroll
                for (int nt = 0; nt < 3; ++nt) {
                    int c = mt * 16 + r4;
                    int j = nt * 8 + l4 * 2;
                    if (j < J_)     smu[OFF_A1 + c * AST + p20 + j]       = f2tf(d[mt][nt][0]);
                    if (j + 1 < J_) smu[OFF_A1 + c * AST + p20 + j + 1]   = f2tf(d[mt][nt][1]);
                    if (j < J_)     smu[OFF_A1 + (c + 8) * AST + p20 + j]     = f2tf(d[mt][nt][2]);
                    if (j + 1 < J_) smu[OFF_A1 + (c + 8) * AST + p20 + j + 1] = f2tf(d[mt][nt][3]);
                }
        }
    }
    __syncthreads();

    // reload SWB = Wts (LT dead now)
    for (int q = tid; q < SWB_U4; q += NTH)
        *(uint4*)&smu[OFF_SWB + q * 4] = *(const uint4*)&g_Wts[q * 4];
    __syncthreads();

    // ================= OUT: Wt * AGG -> stage into A2 (f32) ==================
    mma_phase<0, 0, 0>(sm, OFF_A1, OFF_A2, w, lane);
    __syncthreads();

    // ===== coalesced global store from A2[o][p*20+j] =====
    for (int v = tid; v < 64 * 38; v += NTH) {
        int o = v / 38, rr = v % 38;
        int j = rr >> 1, pb = (rr & 1) * 4;
        const float* src = &sm[OFF_A2 + o * AST + j];
        float4 t = make_float4(src[(pb + 0) * 20], src[(pb + 1) * 20],
                               src[(pb + 2) * 20], src[(pb + 3) * 20]);
        *(float4*)&out[((size_t)((bb * 64 + o) * J_ + j)) * 2560 + ts0 + pb] = t;
    }
}

// ------------------------------ launcher --------------------------------------
extern "C" void kernel_launch(void* const* d_in, const int* in_sizes, int n_in,
                              void* d_out, int out_size) {
    const float* x     = (const float*)d_in[0];
    const float* gamma = (const float*)d_in[1];
    const float* beta  = (const float*)d_in[2];
    const float* w1    = (const float*)d_in[3];
    const float* b1    = (const float*)d_in[4];
    const float* w2    = (const float*)d_in[5];
    const float* b2    = (const float*)d_in[6];
    const float* ws1   = (const float*)d_in[7];
    const float* bs1   = (const float*)d_in[8];
    const float* ws2   = (const float*)d_in[9];
    // d_in[10] = bs2 (softmax-invariant), d_in[11] = W
    const float* W     = (const float*)d_in[11];
    float* out = (float*)d_out;

    cudaFuncSetAttribute(geo_gcn_main_kernel,
                         cudaFuncAttributeMaxDynamicSharedMemorySize, SMEM_BYTES);

    bn_stats_kernel<<<NCH / 8, 256>>>(x, gamma, beta);
    setup_kernel<<<16, 256>>>(w1, ws1, bs1, ws2, w2, W);
    geo_gcn_main_kernel<<<NPIX / PPB, NTH, SMEM_BYTES>>>(x, b1, b2, out);
}